// round 6
// baseline (speedup 1.0000x reference)
#include <cuda_runtime.h>
#include <cuda_fp16.h>

// Problem constants (from reference): N=50000, DIM=64, HEADS=4, E=800000.
#define MAXN 50000
#define MAXE 800000
#define MAXET (MAXE + MAXN)
#define HC 256   // HEADS * DIM

// ---------------- scratch (static device globals; no allocation) ----------------
__device__ __align__(16) __half g_xh[MAXN * HC];      // [N, H, C] = x @ W  (fp16)
__device__ __align__(16) float g_asrc[MAXN * 4];      // [N, H]
__device__ __align__(16) float g_adst[MAXN * 4];      // [N, H]
__device__ int    g_deg[MAXN];
__device__ int    g_off[MAXN + 1];
__device__ int    g_bsum[64];
__device__ int    g_boff[64];
__device__ int    g_rank[MAXET];                      // within-dst rank of each edge
__device__ float4 g_pack[MAXET];                      // CSR rec: {src:int, exp01:h2, exp23:h2, pad}
__device__ int    g_is64;                             // 1 if edge buffer is int64

// ---------------- detect int32 vs int64 edge buffer ----------------
__global__ void detect_kernel(const int* __restrict__ e32) {
    __shared__ int s_any;
    if (threadIdx.x == 0) s_any = 0;
    __syncthreads();
    int any = 0;
    for (int i = threadIdx.x; i < 2048; i += blockDim.x)
        any |= e32[2 * i + 1];
    if (any) atomicOr(&s_any, 1);
    __syncthreads();
    if (threadIdx.x == 0) g_is64 = s_any ? 0 : 1;
}

// ---------------- init counters ----------------
__global__ void init_kernel(int N) {
    int i = blockIdx.x * blockDim.x + threadIdx.x;
    if (i < N) g_deg[i] = 0;
}

// ---------------- GEMM g_xh[N,256] = X[N,64] @ W[64,256]  + fused a_src/a_dst ----------------
__global__ void gemm_kernel(const float* __restrict__ X, const float* __restrict__ W,
                            const float* __restrict__ att_src,
                            const float* __restrict__ att_dst, int N) {
    __shared__ float sx[64][65];
    __shared__ float sw[64][65];
    int row0 = blockIdx.x * 64;
    int hy   = blockIdx.y;          // head
    int col0 = hy * 64;
    int t = threadIdx.x;            // 256 threads

    #pragma unroll
    for (int i = t; i < 64 * 64; i += 256) {
        int k = i >> 6, j = i & 63;
        sw[k][j] = W[k * 256 + col0 + j];
    }
    #pragma unroll
    for (int i = t; i < 64 * 64; i += 256) {
        int r = i >> 6, k = i & 63;
        int row = row0 + r;
        sx[r][k] = (row < N) ? X[row * 64 + k] : 0.0f;
    }
    __syncthreads();

    int tx = t & 15, ty = t >> 4;
    int r0 = ty * 4, c0 = tx * 4;
    float acc[4][4] = {};
    #pragma unroll
    for (int k = 0; k < 64; k++) {
        float b0 = sw[k][c0 + 0], b1 = sw[k][c0 + 1];
        float b2 = sw[k][c0 + 2], b3 = sw[k][c0 + 3];
        #pragma unroll
        for (int i = 0; i < 4; i++) {
            float a = sx[r0 + i][k];
            acc[i][0] += a * b0; acc[i][1] += a * b1;
            acc[i][2] += a * b2; acc[i][3] += a * b3;
        }
    }

    // store fp16 features
    #pragma unroll
    for (int i = 0; i < 4; i++) {
        int row = row0 + r0 + i;
        if (row < N) {
            __half2 h01 = __floats2half2_rn(acc[i][0], acc[i][1]);
            __half2 h23 = __floats2half2_rn(acc[i][2], acc[i][3]);
            __half2* dst = (__half2*)&g_xh[row * HC + col0 + c0];
            dst[0] = h01; dst[1] = h23;
        }
    }

    // fused attention coefficients: a = sum_c x[row,c]*att[h,c]
    float4 as = *(const float4*)&att_src[col0 + c0];
    float4 ad = *(const float4*)&att_dst[col0 + c0];
    #pragma unroll
    for (int i = 0; i < 4; i++) {
        float ps = acc[i][0] * as.x + acc[i][1] * as.y + acc[i][2] * as.z + acc[i][3] * as.w;
        float pd = acc[i][0] * ad.x + acc[i][1] * ad.y + acc[i][2] * ad.z + acc[i][3] * ad.w;
        #pragma unroll
        for (int off = 8; off > 0; off >>= 1) {
            ps += __shfl_down_sync(0xffffffffu, ps, off, 16);
            pd += __shfl_down_sync(0xffffffffu, pd, off, 16);
        }
        if (tx == 0) {
            int row = row0 + r0 + i;
            if (row < N) {
                g_asrc[row * 4 + hy] = ps;
                g_adst[row * 4 + hy] = pd;
            }
        }
    }
}

// ---------------- degree histogram + per-edge rank (decode dst only) ----------------
__global__ void degree_kernel(const int* __restrict__ e32, int N, int E) {
    int e = blockIdx.x * blockDim.x + threadIdx.x;
    int ET = E + N;
    if (e >= ET) return;
    int d;
    if (e < E) d = g_is64 ? e32[2 * E + 2 * e] : e32[E + e];
    else       d = e - E;
    g_rank[e] = atomicAdd(&g_deg[d], 1);
}

// ---------------- 3-kernel scan: deg -> exclusive offsets ----------------
__global__ void scan_local(int N) {     // grid: ceil(N/1024), block 1024
    __shared__ int wsum[32];
    int t = threadIdx.x, lane = t & 31, wid = t >> 5;
    int i = blockIdx.x * 1024 + t;
    int v = (i < N) ? g_deg[i] : 0;
    int x = v;
    #pragma unroll
    for (int o = 1; o < 32; o <<= 1) {
        int y = __shfl_up_sync(0xffffffffu, x, o);
        if (lane >= o) x += y;
    }
    if (lane == 31) wsum[wid] = x;
    __syncthreads();
    if (wid == 0) {
        int w = wsum[lane];
        #pragma unroll
        for (int o = 1; o < 32; o <<= 1) {
            int y = __shfl_up_sync(0xffffffffu, w, o);
            if (lane >= o) w += y;
        }
        wsum[lane] = w;
    }
    __syncthreads();
    int ex = (wid ? wsum[wid - 1] : 0) + x - v;
    if (i < N) g_off[i] = ex;
    if (t == 1023) g_bsum[blockIdx.x] = wsum[31];
}

__global__ void scan_blocks(int nb) {   // 1 block, 64 threads
    int t = threadIdx.x, lane = t & 31, wid = t >> 5;
    __shared__ int w0tot;
    int v = (t < nb) ? g_bsum[t] : 0;
    int x = v;
    #pragma unroll
    for (int o = 1; o < 32; o <<= 1) {
        int y = __shfl_up_sync(0xffffffffu, x, o);
        if (lane >= o) x += y;
    }
    if (wid == 0 && lane == 31) w0tot = x;
    __syncthreads();
    int ex = x - v + (wid ? w0tot : 0);
    if (t < nb) g_boff[t] = ex;
}

__global__ void scan_add(int N, int ET) {
    int i = blockIdx.x * 1024 + threadIdx.x;
    if (i < N) g_off[i] += g_boff[blockIdx.x];
    if (i == 0) g_off[N] = ET;
}

// ---------------- edge pass 2: decode, exp(leakyrelu), scatter packed rec (no atomics) ----------------
__global__ void edge_pass2(const int* __restrict__ e32, int N, int E) {
    int e = blockIdx.x * blockDim.x + threadIdx.x;
    int ET = E + N;
    if (e >= ET) return;
    int s, d;
    if (e < E) {
        if (g_is64) { s = e32[2 * e]; d = e32[2 * E + 2 * e]; }
        else        { s = e32[e];     d = e32[E + e]; }
    } else {
        s = d = e - E;
    }
    float4 as = *(const float4*)&g_asrc[s * 4];
    float4 ad = *(const float4*)&g_adst[d * 4];
    float l0 = as.x + ad.x, l1 = as.y + ad.y, l2 = as.z + ad.z, l3 = as.w + ad.w;
    l0 = l0 > 0.f ? l0 : 0.2f * l0;
    l1 = l1 > 0.f ? l1 : 0.2f * l1;
    l2 = l2 > 0.f ? l2 : 0.2f * l2;
    l3 = l3 > 0.f ? l3 : 0.2f * l3;
    __half2 e01 = __floats2half2_rn(__expf(l0), __expf(l1));
    __half2 e23 = __floats2half2_rn(__expf(l2), __expf(l3));
    float4 rec;
    rec.x = __int_as_float(s);
    rec.y = __uint_as_float(*(const unsigned int*)&e01);
    rec.z = __uint_as_float(*(const unsigned int*)&e23);
    rec.w = 0.0f;
    int pos = g_off[d] + g_rank[e];
    g_pack[pos] = rec;
}

// ---------------- warp-per-dst-node aggregation; head-split lanes, LDG.64 gathers ----------------
// lanes 0-15: heads {0,2}, lanes 16-31: heads {1,3}; lane covers cols 4k..4k+3.
__global__ void aggregate_kernel(const float* __restrict__ bias,
                                 float* __restrict__ out, int N) {
    int gw = (blockIdx.x * blockDim.x + threadIdx.x) >> 5;
    int lane = threadIdx.x & 31;
    if (gw >= N) return;
    int beg = g_off[gw], end = g_off[gw + 1];   // end > beg guaranteed (self-loop)
    int hh = lane >> 4;        // 0 or 1
    int k  = lane & 15;        // col group

    float aA0 = 0.f, aA1 = 0.f, aA2 = 0.f, aA3 = 0.f;   // head hh
    float aB0 = 0.f, aB1 = 0.f, aB2 = 0.f, aB3 = 0.f;   // head hh+2
    float sA = 0.f, sB = 0.f;

    float4 rec = g_pack[beg];
    for (int j = beg; j < end; j++) {
        float4 nrec = (j + 1 < end) ? g_pack[j + 1] : rec;   // prefetch
        int s = __float_as_int(rec.x);
        unsigned int u01 = __float_as_uint(rec.y);
        unsigned int u23 = __float_as_uint(rec.z);
        float2 w01 = __half22float2(*(const __half2*)&u01);
        float2 w23 = __half22float2(*(const __half2*)&u23);
        float wA = hh ? w01.y : w01.x;
        float wB = hh ? w23.y : w23.x;
        const __half2* xr = (const __half2*)(g_xh + s * HC);
        uint2 uA = *(const uint2*)(xr + hh * 32 + 2 * k);
        uint2 uB = *(const uint2*)(xr + (hh + 2) * 32 + 2 * k);
        float2 vA0 = __half22float2(*(const __half2*)&uA.x);
        float2 vA1 = __half22float2(*(const __half2*)&uA.y);
        float2 vB0 = __half22float2(*(const __half2*)&uB.x);
        float2 vB1 = __half22float2(*(const __half2*)&uB.y);
        aA0 += wA * vA0.x; aA1 += wA * vA0.y; aA2 += wA * vA1.x; aA3 += wA * vA1.y;
        aB0 += wB * vB0.x; aB1 += wB * vB0.y; aB2 += wB * vB1.x; aB3 += wB * vB1.y;
        sA += wA; sB += wB;
        rec = nrec;
    }

    float nA = 0.25f / (sA + 1e-16f);
    float nB = 0.25f / (sB + 1e-16f);
    float p0 = aA0 * nA + aB0 * nB;
    float p1 = aA1 * nA + aB1 * nB;
    float p2 = aA2 * nA + aB2 * nB;
    float p3 = aA3 * nA + aB3 * nB;
    // combine head pairs: lane l (heads hh,hh+2) + lane l^16 (heads 1-hh,3-hh)
    p0 += __shfl_xor_sync(0xffffffffu, p0, 16);
    p1 += __shfl_xor_sync(0xffffffffu, p1, 16);
    p2 += __shfl_xor_sync(0xffffffffu, p2, 16);
    p3 += __shfl_xor_sync(0xffffffffu, p3, 16);
    if (lane < 16) {
        float4 b = *(const float4*)&bias[4 * k];
        float4 o = make_float4(p0 + b.x, p1 + b.y, p2 + b.z, p3 + b.w);
        *(float4*)&out[gw * 64 + 4 * k] = o;
    }
}

// ---------------- launch ----------------
extern "C" void kernel_launch(void* const* d_in, const int* in_sizes, int n_in,
                              void* d_out, int out_size) {
    const float* meta_x  = (const float*)d_in[0];
    const int*   edge32  = (const int*)d_in[1];
    const float* W       = (const float*)d_in[2];
    const float* att_src = (const float*)d_in[3];
    const float* att_dst = (const float*)d_in[4];
    const float* bias    = (const float*)d_in[5];
    float*       out     = (float*)d_out;

    int N  = in_sizes[0] / 64;
    int E  = in_sizes[1] / 2;
    int ET = E + N;
    int nb = (N + 1023) / 1024;

    detect_kernel<<<1, 256>>>(edge32);
    init_kernel<<<(N + 255) / 256, 256>>>(N);
    gemm_kernel<<<dim3((N + 63) / 64, 4), 256>>>(meta_x, W, att_src, att_dst, N);
    degree_kernel<<<(ET + 255) / 256, 256>>>(edge32, N, E);
    scan_local<<<nb, 1024>>>(N);
    scan_blocks<<<1, 64>>>(nb);
    scan_add<<<nb, 1024>>>(N, ET);
    edge_pass2<<<(ET + 255) / 256, 256>>>(edge32, N, E);
    aggregate_kernel<<<(N * 32 + 255) / 256, 256>>>(bias, out, N);
}

// round 7
// speedup vs baseline: 1.0455x; 1.0455x over previous
#include <cuda_runtime.h>
#include <cuda_fp16.h>
#include <cstdint>

// Problem constants (from reference): N=50000, DIM=64, HEADS=4, E=800000.
#define MAXN 50000
#define MAXE 800000
#define MAXET (MAXE + MAXN)
#define HC 256   // HEADS * DIM

// ---------------- scratch (static device globals; no allocation) ----------------
__device__ __align__(16) __half g_xh[MAXN * HC];      // [N, H, C] = x @ W  (fp16)
__device__ __align__(16) float g_asrc[MAXN * 4];      // [N, H]
__device__ __align__(16) float g_adst[MAXN * 4];      // [N, H]
__device__ __align__(16) float g_watt[64 * 8];        // [k][j]: j=0..3 src heads, 4..7 dst heads
__device__ int    g_deg[MAXN];
__device__ int    g_off[MAXN + 1];
__device__ int    g_bsum[64];
__device__ int    g_boff[64];
__device__ int    g_rank[MAXET];                      // within-dst rank of each edge
__device__ float4 g_pack[MAXET];                      // CSR rec: {src:int, exp01:h2, exp23:h2, pad}
__device__ int    g_is64;                             // 1 if edge buffer is int64

// ---------------- detect int64 vs int32 + init counters ----------------
__global__ void detect_init_kernel(const int* __restrict__ e32, int N) {
    int i = blockIdx.x * blockDim.x + threadIdx.x;
    if (i < N) g_deg[i] = 0;
    if (blockIdx.x == 0) {
        __shared__ int s_any;
        if (threadIdx.x == 0) s_any = 0;
        __syncthreads();
        int any = 0;
        for (int k = threadIdx.x; k < 2048; k += blockDim.x)
            any |= e32[2 * k + 1];
        if (any) atomicOr(&s_any, 1);
        __syncthreads();
        if (threadIdx.x == 0) g_is64 = s_any ? 0 : 1;
    }
}

// ---------------- tiny: watt[k][j] = sum_c W[k, h*64+c] * att_{src,dst}[h*64+c] ----------------
__global__ void watt_kernel(const float* __restrict__ W,
                            const float* __restrict__ att_src,
                            const float* __restrict__ att_dst) {
    int t = threadIdx.x;                 // 512 threads: t -> (k, j)
    int k = t >> 3, j = t & 7;
    int h = j & 3;
    const float* av = (j < 4) ? att_src : att_dst;
    float acc = 0.f;
    #pragma unroll 16
    for (int c = 0; c < 64; c++)
        acc += W[k * 256 + h * 64 + c] * av[h * 64 + c];
    g_watt[k * 8 + j] = acc;
}

// ---------------- a coefs: a[n,j] = meta_x[n,:] @ watt[:,j]  (fp32, exact assoc) ----------------
__global__ void acoef_kernel(const float* __restrict__ X, int N) {
    __shared__ float sw[64][8];
    int t = threadIdx.x;                 // 256
    #pragma unroll
    for (int i = t; i < 512; i += 256) sw[i >> 3][i & 7] = g_watt[i];
    __syncthreads();
    int n = blockIdx.x * 256 + t;
    if (n >= N) return;
    float a[8] = {};
    const float4* xr = (const float4*)(X + n * 64);
    #pragma unroll
    for (int q = 0; q < 16; q++) {
        float4 v = xr[q];
        int k = q * 4;
        #pragma unroll
        for (int j = 0; j < 8; j++)
            a[j] += v.x * sw[k][j] + v.y * sw[k + 1][j] + v.z * sw[k + 2][j] + v.w * sw[k + 3][j];
    }
    *(float4*)&g_asrc[n * 4] = make_float4(a[0], a[1], a[2], a[3]);
    *(float4*)&g_adst[n * 4] = make_float4(a[4], a[5], a[6], a[7]);
}

// ---------------- HMMA GEMM: g_xh[N,256] = fp16(X[N,64]) @ fp16(W[64,256]) ----------------
// block: 256 thr = 8 warps; 64 rows x 256 cols per block.
// warp w: rows (w&1)*32..+32, cols (w>>1)*64..+64.  mma m16n8k16, fp32 accum.
__global__ void __launch_bounds__(256) gemm_mma_kernel(const float* __restrict__ X,
                                                       const float* __restrict__ W, int N) {
    __shared__ __half sA[64][72];
    __shared__ __half sB[64][264];
    int row0 = blockIdx.x * 64;
    int t = threadIdx.x;

    for (int i = t; i < 64 * 256; i += 256) {
        int k = i >> 8, n = i & 255;
        sB[k][n] = __float2half(W[i]);
    }
    for (int i = t; i < 64 * 64; i += 256) {
        int r = i >> 6, k = i & 63;
        int row = row0 + r;
        sA[r][k] = __float2half(row < N ? X[row * 64 + k] : 0.f);
    }
    __syncthreads();

    int w = t >> 5, lane = t & 31;
    int wr = (w & 1) * 32;          // warp row offset within tile
    int wc = (w >> 1) * 64;         // warp col offset (head*64)
    int m8 = lane >> 3, i8 = lane & 7;
    int rg = (m8 & 1) * 8 + i8;     // ldmatrix row within 16
    int cg = (m8 >> 1) * 8;         // ldmatrix col group

    float acc[2][8][4] = {};

    #pragma unroll
    for (int ki = 0; ki < 4; ki++) {
        uint32_t a[2][4];
        #pragma unroll
        for (int mi = 0; mi < 2; mi++) {
            uint32_t addr = (uint32_t)__cvta_generic_to_shared(
                &sA[wr + mi * 16 + rg][ki * 16 + cg]);
            asm volatile("ldmatrix.sync.aligned.m8n8.x4.shared.b16 {%0,%1,%2,%3}, [%4];"
                         : "=r"(a[mi][0]), "=r"(a[mi][1]), "=r"(a[mi][2]), "=r"(a[mi][3])
                         : "r"(addr));
        }
        uint32_t b[8][2];
        #pragma unroll
        for (int nj = 0; nj < 4; nj++) {
            uint32_t addr = (uint32_t)__cvta_generic_to_shared(
                &sB[ki * 16 + rg][wc + nj * 16 + cg]);
            uint32_t r0, r1, r2, r3;
            asm volatile("ldmatrix.sync.aligned.m8n8.x4.trans.shared.b16 {%0,%1,%2,%3}, [%4];"
                         : "=r"(r0), "=r"(r1), "=r"(r2), "=r"(r3)
                         : "r"(addr));
            b[nj * 2][0] = r0;     b[nj * 2][1] = r1;
            b[nj * 2 + 1][0] = r2; b[nj * 2 + 1][1] = r3;
        }
        #pragma unroll
        for (int mi = 0; mi < 2; mi++)
            #pragma unroll
            for (int ni = 0; ni < 8; ni++) {
                asm volatile(
                    "mma.sync.aligned.m16n8k16.row.col.f32.f16.f16.f32 "
                    "{%0,%1,%2,%3}, {%4,%5,%6,%7}, {%8,%9}, {%0,%1,%2,%3};"
                    : "+f"(acc[mi][ni][0]), "+f"(acc[mi][ni][1]),
                      "+f"(acc[mi][ni][2]), "+f"(acc[mi][ni][3])
                    : "r"(a[mi][0]), "r"(a[mi][1]), "r"(a[mi][2]), "r"(a[mi][3]),
                      "r"(b[ni][0]), "r"(b[ni][1]));
            }
    }

    // epilogue: store fp16
    int rrow = lane >> 2, rcol = (lane & 3) * 2;
    #pragma unroll
    for (int mi = 0; mi < 2; mi++) {
        #pragma unroll
        for (int ni = 0; ni < 8; ni++) {
            int row = row0 + wr + mi * 16 + rrow;
            int col = wc + ni * 8 + rcol;
            if (row < N) {
                *(__half2*)&g_xh[row * HC + col] =
                    __floats2half2_rn(acc[mi][ni][0], acc[mi][ni][1]);
            }
            if (row + 8 < N) {
                *(__half2*)&g_xh[(row + 8) * HC + col] =
                    __floats2half2_rn(acc[mi][ni][2], acc[mi][ni][3]);
            }
        }
    }
}

// ---------------- degree histogram + per-edge rank (decode dst only) ----------------
__global__ void degree_kernel(const int* __restrict__ e32, int N, int E) {
    int e = blockIdx.x * blockDim.x + threadIdx.x;
    int ET = E + N;
    if (e >= ET) return;
    int d;
    if (e < E) d = g_is64 ? e32[2 * E + 2 * e] : e32[E + e];
    else       d = e - E;
    g_rank[e] = atomicAdd(&g_deg[d], 1);
}

// ---------------- 3-kernel scan: deg -> exclusive offsets ----------------
__global__ void scan_local(int N) {
    __shared__ int wsum[32];
    int t = threadIdx.x, lane = t & 31, wid = t >> 5;
    int i = blockIdx.x * 1024 + t;
    int v = (i < N) ? g_deg[i] : 0;
    int x = v;
    #pragma unroll
    for (int o = 1; o < 32; o <<= 1) {
        int y = __shfl_up_sync(0xffffffffu, x, o);
        if (lane >= o) x += y;
    }
    if (lane == 31) wsum[wid] = x;
    __syncthreads();
    if (wid == 0) {
        int w = wsum[lane];
        #pragma unroll
        for (int o = 1; o < 32; o <<= 1) {
            int y = __shfl_up_sync(0xffffffffu, w, o);
            if (lane >= o) w += y;
        }
        wsum[lane] = w;
    }
    __syncthreads();
    int ex = (wid ? wsum[wid - 1] : 0) + x - v;
    if (i < N) g_off[i] = ex;
    if (t == 1023) g_bsum[blockIdx.x] = wsum[31];
}

__global__ void scan_blocks(int nb) {
    int t = threadIdx.x, lane = t & 31, wid = t >> 5;
    __shared__ int w0tot;
    int v = (t < nb) ? g_bsum[t] : 0;
    int x = v;
    #pragma unroll
    for (int o = 1; o < 32; o <<= 1) {
        int y = __shfl_up_sync(0xffffffffu, x, o);
        if (lane >= o) x += y;
    }
    if (wid == 0 && lane == 31) w0tot = x;
    __syncthreads();
    int ex = x - v + (wid ? w0tot : 0);
    if (t < nb) g_boff[t] = ex;
}

__global__ void scan_add(int N, int ET) {
    int i = blockIdx.x * 1024 + threadIdx.x;
    if (i < N) g_off[i] += g_boff[blockIdx.x];
    if (i == 0) g_off[N] = ET;
}

// ---------------- edge pass 2: decode, exp(leakyrelu), scatter packed rec (no atomics) ----------------
__global__ void edge_pass2(const int* __restrict__ e32, int N, int E) {
    int e = blockIdx.x * blockDim.x + threadIdx.x;
    int ET = E + N;
    if (e >= ET) return;
    int s, d;
    if (e < E) {
        if (g_is64) { s = e32[2 * e]; d = e32[2 * E + 2 * e]; }
        else        { s = e32[e];     d = e32[E + e]; }
    } else {
        s = d = e - E;
    }
    float4 as = *(const float4*)&g_asrc[s * 4];
    float4 ad = *(const float4*)&g_adst[d * 4];
    float l0 = as.x + ad.x, l1 = as.y + ad.y, l2 = as.z + ad.z, l3 = as.w + ad.w;
    l0 = l0 > 0.f ? l0 : 0.2f * l0;
    l1 = l1 > 0.f ? l1 : 0.2f * l1;
    l2 = l2 > 0.f ? l2 : 0.2f * l2;
    l3 = l3 > 0.f ? l3 : 0.2f * l3;
    __half2 e01 = __floats2half2_rn(__expf(l0), __expf(l1));
    __half2 e23 = __floats2half2_rn(__expf(l2), __expf(l3));
    float4 rec;
    rec.x = __int_as_float(s);
    rec.y = __uint_as_float(*(const unsigned int*)&e01);
    rec.z = __uint_as_float(*(const unsigned int*)&e23);
    rec.w = 0.0f;
    int pos = g_off[d] + g_rank[e];
    g_pack[pos] = rec;
}

// ---------------- warp-per-dst-node aggregation; segsum computed in-loop (R5 body) ----------------
__global__ void aggregate_kernel(const float* __restrict__ bias,
                                 float* __restrict__ out, int N) {
    int gw = (blockIdx.x * blockDim.x + threadIdx.x) >> 5;
    int lane = threadIdx.x & 31;
    if (gw >= N) return;
    int beg = g_off[gw], end = g_off[gw + 1];
    float a00 = 0.f, a01 = 0.f, a10 = 0.f, a11 = 0.f;
    float a20 = 0.f, a21 = 0.f, a30 = 0.f, a31 = 0.f;
    float s0 = 0.f, s1 = 0.f, s2 = 0.f, s3 = 0.f;
    for (int j = beg; j < end; j++) {
        float4 rec = g_pack[j];
        int s = __float_as_int(rec.x);
        unsigned int u01 = __float_as_uint(rec.y);
        unsigned int u23 = __float_as_uint(rec.z);
        float2 w01 = __half22float2(*(const __half2*)&u01);
        float2 w23 = __half22float2(*(const __half2*)&u23);
        const __half2* xr = (const __half2*)(g_xh + s * HC);
        float2 v0 = __half22float2(xr[lane]);
        float2 v1 = __half22float2(xr[32 + lane]);
        float2 v2 = __half22float2(xr[64 + lane]);
        float2 v3 = __half22float2(xr[96 + lane]);
        a00 += w01.x * v0.x; a01 += w01.x * v0.y;
        a10 += w01.y * v1.x; a11 += w01.y * v1.y;
        a20 += w23.x * v2.x; a21 += w23.x * v2.y;
        a30 += w23.y * v3.x; a31 += w23.y * v3.y;
        s0 += w01.x; s1 += w01.y; s2 += w23.x; s3 += w23.y;
    }
    float n0 = 0.25f / (s0 + 1e-16f);
    float n1 = 0.25f / (s1 + 1e-16f);
    float n2 = 0.25f / (s2 + 1e-16f);
    float n3 = 0.25f / (s3 + 1e-16f);
    int c = 2 * lane;
    float o0 = a00 * n0 + a10 * n1 + a20 * n2 + a30 * n3 + bias[c];
    float o1 = a01 * n0 + a11 * n1 + a21 * n2 + a31 * n3 + bias[c + 1];
    *(float2*)&out[gw * 64 + c] = make_float2(o0, o1);
}

// ---------------- launch ----------------
extern "C" void kernel_launch(void* const* d_in, const int* in_sizes, int n_in,
                              void* d_out, int out_size) {
    const float* meta_x  = (const float*)d_in[0];
    const int*   edge32  = (const int*)d_in[1];
    const float* W       = (const float*)d_in[2];
    const float* att_src = (const float*)d_in[3];
    const float* att_dst = (const float*)d_in[4];
    const float* bias    = (const float*)d_in[5];
    float*       out     = (float*)d_out;

    int N  = in_sizes[0] / 64;
    int E  = in_sizes[1] / 2;
    int ET = E + N;
    int nb = (N + 1023) / 1024;

    detect_init_kernel<<<(N + 255) / 256, 256>>>(edge32, N);
    watt_kernel<<<1, 512>>>(W, att_src, att_dst);
    acoef_kernel<<<(N + 255) / 256, 256>>>(meta_x, N);
    gemm_mma_kernel<<<(N + 63) / 64, 256>>>(meta_x, W, N);
    degree_kernel<<<(ET + 255) / 256, 256>>>(edge32, N, E);
    scan_local<<<nb, 1024>>>(N);
    scan_blocks<<<1, 64>>>(nb);
    scan_add<<<nb, 1024>>>(N, ET);
    edge_pass2<<<(ET + 255) / 256, 256>>>(edge32, N, E);
    aggregate_kernel<<<(N * 32 + 255) / 256, 256>>>(bias, out, N);
}

// round 8
// speedup vs baseline: 1.1889x; 1.1372x over previous
#include <cuda_runtime.h>
#include <cuda_fp16.h>
#include <cstdint>

// Problem constants (from reference): N=50000, DIM=64, HEADS=4, E=800000.
#define MAXN 50000
#define MAXE 800000
#define MAXET (MAXE + MAXN)
#define HC 256   // HEADS * DIM

// ---------------- scratch (static device globals; no allocation) ----------------
__device__ __align__(16) __half g_xh[MAXN * HC];      // [N, H, C] = x @ W  (fp16)
__device__ __align__(16) __half g_wh[64 * 256];       // fp16 copy of W
__device__ __align__(16) float g_asrc[MAXN * 4];      // [N, H]
__device__ __align__(16) float g_adst[MAXN * 4];      // [N, H]
__device__ __align__(16) float g_watt[64 * 8];        // [k][j]: j=0..3 src, 4..7 dst
__device__ int    g_deg[MAXN];
__device__ int    g_off[MAXN + 1];
__device__ int    g_bsum[64];
__device__ int    g_boff[64];
__device__ int    g_rank[MAXET];                      // within-dst rank of each edge
__device__ float4 g_pack[MAXET];                      // CSR rec: {src:int, exp01:h2, exp23:h2, pad}
__device__ int    g_is64;                             // 1 if edge buffer is int64

// ---------------- detect int64 vs int32 + init counters ----------------
__global__ void detect_init_kernel(const int* __restrict__ e32, int N) {
    int i = blockIdx.x * blockDim.x + threadIdx.x;
    if (i < N) g_deg[i] = 0;
    if (blockIdx.x == 0) {
        __shared__ int s_any;
        if (threadIdx.x == 0) s_any = 0;
        __syncthreads();
        int any = 0;
        for (int k = threadIdx.x; k < 2048; k += blockDim.x)
            any |= e32[2 * k + 1];
        if (any) atomicOr(&s_any, 1);
        __syncthreads();
        if (threadIdx.x == 0) g_is64 = s_any ? 0 : 1;
    }
}

// ---------------- one-shot: W -> fp16 ----------------
__global__ void wh_kernel(const float* __restrict__ W) {
    int i = blockIdx.x * blockDim.x + threadIdx.x;   // 4096 threads, 4 floats each
    float4 v = *(const float4*)&W[i * 4];
    __half2 h01 = __floats2half2_rn(v.x, v.y);
    __half2 h23 = __floats2half2_rn(v.z, v.w);
    *(__half2*)&g_wh[i * 4]     = h01;
    *(__half2*)&g_wh[i * 4 + 2] = h23;
}

// ---------------- tiny: watt[k][j] = sum_c W[k, h*64+c] * att_{src,dst}[h*64+c] ----------------
__global__ void watt_kernel(const float* __restrict__ W,
                            const float* __restrict__ att_src,
                            const float* __restrict__ att_dst) {
    int t = threadIdx.x;                 // 512 threads: t -> (k, j)
    int k = t >> 3, j = t & 7;
    int h = j & 3;
    const float* av = (j < 4) ? att_src : att_dst;
    float acc = 0.f;
    #pragma unroll 16
    for (int c = 0; c < 64; c++)
        acc += W[k * 256 + h * 64 + c] * av[h * 64 + c];
    g_watt[k * 8 + j] = acc;
}

// ---------------- a coefs: a[n,j] = meta_x[n,:] @ watt[:,j]  (fp32) ----------------
__global__ void acoef_kernel(const float* __restrict__ X, int N) {
    __shared__ float sw[64][8];
    int t = threadIdx.x;                 // 256
    #pragma unroll
    for (int i = t; i < 512; i += 256) sw[i >> 3][i & 7] = g_watt[i];
    __syncthreads();
    int n = blockIdx.x * 256 + t;
    if (n >= N) return;
    float a[8] = {};
    const float4* xr = (const float4*)(X + n * 64);
    #pragma unroll
    for (int q = 0; q < 16; q++) {
        float4 v = xr[q];
        int k = q * 4;
        #pragma unroll
        for (int j = 0; j < 8; j++)
            a[j] += v.x * sw[k][j] + v.y * sw[k + 1][j] + v.z * sw[k + 2][j] + v.w * sw[k + 3][j];
    }
    *(float4*)&g_asrc[n * 4] = make_float4(a[0], a[1], a[2], a[3]);
    *(float4*)&g_adst[n * 4] = make_float4(a[4], a[5], a[6], a[7]);
}

// ---------------- HMMA GEMM: g_xh[N,256] = fp16(X[N,64]) @ g_wh[64,256] ----------------
// 512 threads = 16 warps; block tile 64 rows x 256 cols.
// warp w: rows (w&3)*16 .. +16, cols (w>>2)*64 .. +64.  mma m16n8k16, fp32 accum.
__global__ void __launch_bounds__(512, 2) gemm_mma_kernel(const float* __restrict__ X, int N) {
    __shared__ __half sA[64][72];
    __shared__ __half sB[64][264];
    int row0 = blockIdx.x * 64;
    int t = threadIdx.x;

    // stage W fp16: 16384 halves = 2048 uint4; 4 iters
    #pragma unroll
    for (int i = t; i < 2048; i += 512) {
        int idx = i * 8;
        int k = idx >> 8, n = idx & 255;
        *(uint4*)&sB[k][n] = *(const uint4*)&g_wh[idx];
    }
    // stage X: 64*64 floats = 1024 float4; 2 iters
    #pragma unroll
    for (int i = t; i < 1024; i += 512) {
        int idx = i * 4;
        int r = idx >> 6, k = idx & 63;
        int row = row0 + r;
        float4 v = (row < N) ? *(const float4*)&X[row * 64 + k]
                             : make_float4(0.f, 0.f, 0.f, 0.f);
        *(__half2*)&sA[r][k]     = __floats2half2_rn(v.x, v.y);
        *(__half2*)&sA[r][k + 2] = __floats2half2_rn(v.z, v.w);
    }
    __syncthreads();

    int w = t >> 5, lane = t & 31;
    int wr = (w & 3) * 16;          // warp row offset
    int wc = (w >> 2) * 64;         // warp col offset
    int m8 = lane >> 3, i8 = lane & 7;
    int rg = (m8 & 1) * 8 + i8;     // ldmatrix row within 16
    int cg = (m8 >> 1) * 8;         // ldmatrix col group

    float acc[8][4] = {};

    #pragma unroll
    for (int ki = 0; ki < 4; ki++) {
        uint32_t a0, a1, a2, a3;
        {
            uint32_t addr = (uint32_t)__cvta_generic_to_shared(
                &sA[wr + rg][ki * 16 + cg]);
            asm volatile("ldmatrix.sync.aligned.m8n8.x4.shared.b16 {%0,%1,%2,%3}, [%4];"
                         : "=r"(a0), "=r"(a1), "=r"(a2), "=r"(a3) : "r"(addr));
        }
        #pragma unroll
        for (int nj = 0; nj < 4; nj++) {
            uint32_t b0, b1, b2, b3;
            uint32_t addr = (uint32_t)__cvta_generic_to_shared(
                &sB[ki * 16 + rg][wc + nj * 16 + cg]);
            asm volatile("ldmatrix.sync.aligned.m8n8.x4.trans.shared.b16 {%0,%1,%2,%3}, [%4];"
                         : "=r"(b0), "=r"(b1), "=r"(b2), "=r"(b3) : "r"(addr));
            asm volatile(
                "mma.sync.aligned.m16n8k16.row.col.f32.f16.f16.f32 "
                "{%0,%1,%2,%3}, {%4,%5,%6,%7}, {%8,%9}, {%0,%1,%2,%3};"
                : "+f"(acc[nj * 2][0]), "+f"(acc[nj * 2][1]),
                  "+f"(acc[nj * 2][2]), "+f"(acc[nj * 2][3])
                : "r"(a0), "r"(a1), "r"(a2), "r"(a3), "r"(b0), "r"(b1));
            asm volatile(
                "mma.sync.aligned.m16n8k16.row.col.f32.f16.f16.f32 "
                "{%0,%1,%2,%3}, {%4,%5,%6,%7}, {%8,%9}, {%0,%1,%2,%3};"
                : "+f"(acc[nj * 2 + 1][0]), "+f"(acc[nj * 2 + 1][1]),
                  "+f"(acc[nj * 2 + 1][2]), "+f"(acc[nj * 2 + 1][3])
                : "r"(a0), "r"(a1), "r"(a2), "r"(a3), "r"(b2), "r"(b3));
        }
    }

    // epilogue: fp16 stores
    int rrow = lane >> 2, rcol = (lane & 3) * 2;
    int row = row0 + wr + rrow;
    #pragma unroll
    for (int ni = 0; ni < 8; ni++) {
        int col = wc + ni * 8 + rcol;
        if (row < N)
            *(__half2*)&g_xh[row * HC + col] = __floats2half2_rn(acc[ni][0], acc[ni][1]);
        if (row + 8 < N)
            *(__half2*)&g_xh[(row + 8) * HC + col] = __floats2half2_rn(acc[ni][2], acc[ni][3]);
    }
}

// ---------------- degree histogram + per-edge rank (decode dst only) ----------------
__global__ void degree_kernel(const int* __restrict__ e32, int N, int E) {
    int e = blockIdx.x * blockDim.x + threadIdx.x;
    int ET = E + N;
    if (e >= ET) return;
    int d;
    if (e < E) d = g_is64 ? e32[2 * E + 2 * e] : e32[E + e];
    else       d = e - E;
    g_rank[e] = atomicAdd(&g_deg[d], 1);
}

// ---------------- 3-kernel scan: deg -> exclusive offsets ----------------
__global__ void scan_local(int N) {
    __shared__ int wsum[32];
    int t = threadIdx.x, lane = t & 31, wid = t >> 5;
    int i = blockIdx.x * 1024 + t;
    int v = (i < N) ? g_deg[i] : 0;
    int x = v;
    #pragma unroll
    for (int o = 1; o < 32; o <<= 1) {
        int y = __shfl_up_sync(0xffffffffu, x, o);
        if (lane >= o) x += y;
    }
    if (lane == 31) wsum[wid] = x;
    __syncthreads();
    if (wid == 0) {
        int w = wsum[lane];
        #pragma unroll
        for (int o = 1; o < 32; o <<= 1) {
            int y = __shfl_up_sync(0xffffffffu, w, o);
            if (lane >= o) w += y;
        }
        wsum[lane] = w;
    }
    __syncthreads();
    int ex = (wid ? wsum[wid - 1] : 0) + x - v;
    if (i < N) g_off[i] = ex;
    if (t == 1023) g_bsum[blockIdx.x] = wsum[31];
}

__global__ void scan_blocks(int nb) {
    int t = threadIdx.x, lane = t & 31, wid = t >> 5;
    __shared__ int w0tot;
    int v = (t < nb) ? g_bsum[t] : 0;
    int x = v;
    #pragma unroll
    for (int o = 1; o < 32; o <<= 1) {
        int y = __shfl_up_sync(0xffffffffu, x, o);
        if (lane >= o) x += y;
    }
    if (wid == 0 && lane == 31) w0tot = x;
    __syncthreads();
    int ex = x - v + (wid ? w0tot : 0);
    if (t < nb) g_boff[t] = ex;
}

__global__ void scan_add(int N, int ET) {
    int i = blockIdx.x * 1024 + threadIdx.x;
    if (i < N) g_off[i] += g_boff[blockIdx.x];
    if (i == 0) g_off[N] = ET;
}

// ---------------- edge pass 2: decode, exp(leakyrelu), scatter packed rec ----------------
__global__ void edge_pass2(const int* __restrict__ e32, int N, int E) {
    int e = blockIdx.x * blockDim.x + threadIdx.x;
    int ET = E + N;
    if (e >= ET) return;
    int s, d;
    if (e < E) {
        if (g_is64) { s = e32[2 * e]; d = e32[2 * E + 2 * e]; }
        else        { s = e32[e];     d = e32[E + e]; }
    } else {
        s = d = e - E;
    }
    float4 as = *(const float4*)&g_asrc[s * 4];
    float4 ad = *(const float4*)&g_adst[d * 4];
    float l0 = as.x + ad.x, l1 = as.y + ad.y, l2 = as.z + ad.z, l3 = as.w + ad.w;
    l0 = l0 > 0.f ? l0 : 0.2f * l0;
    l1 = l1 > 0.f ? l1 : 0.2f * l1;
    l2 = l2 > 0.f ? l2 : 0.2f * l2;
    l3 = l3 > 0.f ? l3 : 0.2f * l3;
    __half2 e01 = __floats2half2_rn(__expf(l0), __expf(l1));
    __half2 e23 = __floats2half2_rn(__expf(l2), __expf(l3));
    float4 rec;
    rec.x = __int_as_float(s);
    rec.y = __uint_as_float(*(const unsigned int*)&e01);
    rec.z = __uint_as_float(*(const unsigned int*)&e23);
    rec.w = 0.0f;
    int pos = g_off[d] + g_rank[e];
    g_pack[pos] = rec;
}

// ---------------- warp-per-dst-node aggregation; segsum computed in-loop ----------------
__global__ void aggregate_kernel(const float* __restrict__ bias,
                                 float* __restrict__ out, int N) {
    int gw = (blockIdx.x * blockDim.x + threadIdx.x) >> 5;
    int lane = threadIdx.x & 31;
    if (gw >= N) return;
    int beg = g_off[gw], end = g_off[gw + 1];
    float a00 = 0.f, a01 = 0.f, a10 = 0.f, a11 = 0.f;
    float a20 = 0.f, a21 = 0.f, a30 = 0.f, a31 = 0.f;
    float s0 = 0.f, s1 = 0.f, s2 = 0.f, s3 = 0.f;
    for (int j = beg; j < end; j++) {
        float4 rec = g_pack[j];
        int s = __float_as_int(rec.x);
        unsigned int u01 = __float_as_uint(rec.y);
        unsigned int u23 = __float_as_uint(rec.z);
        float2 w01 = __half22float2(*(const __half2*)&u01);
        float2 w23 = __half22float2(*(const __half2*)&u23);
        const __half2* xr = (const __half2*)(g_xh + s * HC);
        float2 v0 = __half22float2(xr[lane]);
        float2 v1 = __half22float2(xr[32 + lane]);
        float2 v2 = __half22float2(xr[64 + lane]);
        float2 v3 = __half22float2(xr[96 + lane]);
        a00 += w01.x * v0.x; a01 += w01.x * v0.y;
        a10 += w01.y * v1.x; a11 += w01.y * v1.y;
        a20 += w23.x * v2.x; a21 += w23.x * v2.y;
        a30 += w23.y * v3.x; a31 += w23.y * v3.y;
        s0 += w01.x; s1 += w01.y; s2 += w23.x; s3 += w23.y;
    }
    float n0 = 0.25f / (s0 + 1e-16f);
    float n1 = 0.25f / (s1 + 1e-16f);
    float n2 = 0.25f / (s2 + 1e-16f);
    float n3 = 0.25f / (s3 + 1e-16f);
    int c = 2 * lane;
    float o0 = a00 * n0 + a10 * n1 + a20 * n2 + a30 * n3 + bias[c];
    float o1 = a01 * n0 + a11 * n1 + a21 * n2 + a31 * n3 + bias[c + 1];
    *(float2*)&out[gw * 64 + c] = make_float2(o0, o1);
}

// ---------------- launch ----------------
extern "C" void kernel_launch(void* const* d_in, const int* in_sizes, int n_in,
                              void* d_out, int out_size) {
    const float* meta_x  = (const float*)d_in[0];
    const int*   edge32  = (const int*)d_in[1];
    const float* W       = (const float*)d_in[2];
    const float* att_src = (const float*)d_in[3];
    const float* att_dst = (const float*)d_in[4];
    const float* bias    = (const float*)d_in[5];
    float*       out     = (float*)d_out;

    int N  = in_sizes[0] / 64;
    int E  = in_sizes[1] / 2;
    int ET = E + N;
    int nb = (N + 1023) / 1024;

    detect_init_kernel<<<(N + 255) / 256, 256>>>(edge32, N);
    wh_kernel<<<16, 256>>>(W);
    watt_kernel<<<1, 512>>>(W, att_src, att_dst);
    acoef_kernel<<<(N + 255) / 256, 256>>>(meta_x, N);
    gemm_mma_kernel<<<(N + 63) / 64, 512>>>(meta_x, N);
    degree_kernel<<<(ET + 255) / 256, 256>>>(edge32, N, E);
    scan_local<<<nb, 1024>>>(N);
    scan_blocks<<<1, 64>>>(nb);
    scan_add<<<nb, 1024>>>(N, ET);
    edge_pass2<<<(ET + 255) / 256, 256>>>(edge32, N, E);
    aggregate_kernel<<<(N * 32 + 255) / 256, 256>>>(bias, out, N);
}

// round 9
// speedup vs baseline: 1.4014x; 1.1788x over previous
#include <cuda_runtime.h>
#include <cuda_fp16.h>
#include <cstdint>

// Problem constants (from reference): N=50000, DIM=64, HEADS=4, E=800000.
#define MAXN 50000
#define MAXE 800000
#define MAXET (MAXE + MAXN)
#define HC 256   // HEADS * DIM

// ---------------- scratch (static device globals; no allocation) ----------------
__device__ __align__(16) __half g_xh[MAXN * HC];      // [N, H, C] = x @ W  (fp16)
__device__ __align__(16) __half g_wh[64 * 256];       // fp16 copy of W
__device__ __align__(16) float g_asrc[MAXN * 4];      // [N, H]
__device__ __align__(16) float g_adst[MAXN * 4];      // [N, H]
__device__ int    g_deg[MAXN];
__device__ int    g_off[MAXN + 1];
__device__ int    g_bsum[64];
__device__ int    g_boff[64];
__device__ int    g_rank[MAXET];                      // within-dst rank of each edge
__device__ float4 g_pack[MAXET];                      // CSR rec: {src:int, exp01:h2, exp23:h2, pad}
__device__ int    g_is64;                             // 1 if edge buffer is int64

// ---------------- detect int64 vs int32 + init counters ----------------
__global__ void detect_init_kernel(const int* __restrict__ e32, int N) {
    int i = blockIdx.x * blockDim.x + threadIdx.x;
    if (i < N) g_deg[i] = 0;
    if (blockIdx.x == 0) {
        __shared__ int s_any;
        if (threadIdx.x == 0) s_any = 0;
        __syncthreads();
        int any = 0;
        for (int k = threadIdx.x; k < 2048; k += blockDim.x)
            any |= e32[2 * k + 1];
        if (any) atomicOr(&s_any, 1);
        __syncthreads();
        if (threadIdx.x == 0) g_is64 = s_any ? 0 : 1;
    }
}

// ---------------- one-shot: W -> fp16 ----------------
__global__ void wh_kernel(const float* __restrict__ W) {
    int i = blockIdx.x * blockDim.x + threadIdx.x;   // 4096 threads, 4 floats each
    float4 v = *(const float4*)&W[i * 4];
    *(__half2*)&g_wh[i * 4]     = __floats2half2_rn(v.x, v.y);
    *(__half2*)&g_wh[i * 4 + 2] = __floats2half2_rn(v.z, v.w);
}

// ---------------- HMMA GEMM: g_xh[N,256] = fp16(X[N,64]) @ g_wh[64,256] ----------------
// 512 threads = 16 warps; block tile 64 rows x 256 cols.
// warp w: rows (w&3)*16 .. +16, cols (w>>2)*64 .. +64 (head w>>2).
// Fused epilogue: a_src/a_dst per (row, head) from fp32 accumulators.
__global__ void __launch_bounds__(512, 2) gemm_mma_kernel(const float* __restrict__ X,
                                                          const float* __restrict__ att_src,
                                                          const float* __restrict__ att_dst,
                                                          int N) {
    __shared__ __half sA[64][72];
    __shared__ __half sB[64][264];
    int row0 = blockIdx.x * 64;
    int t = threadIdx.x;

    // stage W fp16: 16384 halves = 2048 uint4
    #pragma unroll
    for (int i = t; i < 2048; i += 512) {
        int idx = i * 8;
        int k = idx >> 8, n = idx & 255;
        *(uint4*)&sB[k][n] = *(const uint4*)&g_wh[idx];
    }
    // stage X: 64*64 floats = 1024 float4
    #pragma unroll
    for (int i = t; i < 1024; i += 512) {
        int idx = i * 4;
        int r = idx >> 6, k = idx & 63;
        int row = row0 + r;
        float4 v = (row < N) ? *(const float4*)&X[row * 64 + k]
                             : make_float4(0.f, 0.f, 0.f, 0.f);
        *(__half2*)&sA[r][k]     = __floats2half2_rn(v.x, v.y);
        *(__half2*)&sA[r][k + 2] = __floats2half2_rn(v.z, v.w);
    }
    __syncthreads();

    int w = t >> 5, lane = t & 31;
    int wr = (w & 3) * 16;          // warp row offset
    int h  = w >> 2;                // head
    int wc = h * 64;                // warp col offset
    int m8 = lane >> 3, i8 = lane & 7;
    int rg = (m8 & 1) * 8 + i8;
    int cg = (m8 >> 1) * 8;

    float acc[8][4] = {};

    #pragma unroll
    for (int ki = 0; ki < 4; ki++) {
        uint32_t a0, a1, a2, a3;
        {
            uint32_t addr = (uint32_t)__cvta_generic_to_shared(
                &sA[wr + rg][ki * 16 + cg]);
            asm volatile("ldmatrix.sync.aligned.m8n8.x4.shared.b16 {%0,%1,%2,%3}, [%4];"
                         : "=r"(a0), "=r"(a1), "=r"(a2), "=r"(a3) : "r"(addr));
        }
        #pragma unroll
        for (int nj = 0; nj < 4; nj++) {
            uint32_t b0, b1, b2, b3;
            uint32_t addr = (uint32_t)__cvta_generic_to_shared(
                &sB[ki * 16 + rg][wc + nj * 16 + cg]);
            asm volatile("ldmatrix.sync.aligned.m8n8.x4.trans.shared.b16 {%0,%1,%2,%3}, [%4];"
                         : "=r"(b0), "=r"(b1), "=r"(b2), "=r"(b3) : "r"(addr));
            asm volatile(
                "mma.sync.aligned.m16n8k16.row.col.f32.f16.f16.f32 "
                "{%0,%1,%2,%3}, {%4,%5,%6,%7}, {%8,%9}, {%0,%1,%2,%3};"
                : "+f"(acc[nj * 2][0]), "+f"(acc[nj * 2][1]),
                  "+f"(acc[nj * 2][2]), "+f"(acc[nj * 2][3])
                : "r"(a0), "r"(a1), "r"(a2), "r"(a3), "r"(b0), "r"(b1));
            asm volatile(
                "mma.sync.aligned.m16n8k16.row.col.f32.f16.f16.f32 "
                "{%0,%1,%2,%3}, {%4,%5,%6,%7}, {%8,%9}, {%0,%1,%2,%3};"
                : "+f"(acc[nj * 2 + 1][0]), "+f"(acc[nj * 2 + 1][1]),
                  "+f"(acc[nj * 2 + 1][2]), "+f"(acc[nj * 2 + 1][3])
                : "r"(a0), "r"(a1), "r"(a2), "r"(a3), "r"(b2), "r"(b3));
        }
    }

    // epilogue: fp16 stores + fused attention coefficients
    int rrow = lane >> 2, rcol = (lane & 3) * 2;
    int row = row0 + wr + rrow;
    float ps = 0.f, pd = 0.f, ps8 = 0.f, pd8 = 0.f;
    #pragma unroll
    for (int ni = 0; ni < 8; ni++) {
        int col = wc + ni * 8 + rcol;
        if (row < N)
            *(__half2*)&g_xh[row * HC + col] = __floats2half2_rn(acc[ni][0], acc[ni][1]);
        if (row + 8 < N)
            *(__half2*)&g_xh[(row + 8) * HC + col] = __floats2half2_rn(acc[ni][2], acc[ni][3]);
        float2 as2 = *(const float2*)&att_src[col];
        float2 ad2 = *(const float2*)&att_dst[col];
        ps  += acc[ni][0] * as2.x + acc[ni][1] * as2.y;
        pd  += acc[ni][0] * ad2.x + acc[ni][1] * ad2.y;
        ps8 += acc[ni][2] * as2.x + acc[ni][3] * as2.y;
        pd8 += acc[ni][2] * ad2.x + acc[ni][3] * ad2.y;
    }
    // reduce over the 4 lanes of each row quad (lane&3 varies)
    #pragma unroll
    for (int o = 1; o < 4; o <<= 1) {
        ps  += __shfl_xor_sync(0xffffffffu, ps,  o);
        pd  += __shfl_xor_sync(0xffffffffu, pd,  o);
        ps8 += __shfl_xor_sync(0xffffffffu, ps8, o);
        pd8 += __shfl_xor_sync(0xffffffffu, pd8, o);
    }
    if ((lane & 3) == 0) {
        if (row < N) {
            g_asrc[row * 4 + h] = ps;
            g_adst[row * 4 + h] = pd;
        }
        if (row + 8 < N) {
            g_asrc[(row + 8) * 4 + h] = ps8;
            g_adst[(row + 8) * 4 + h] = pd8;
        }
    }
}

// ---------------- degree histogram + per-edge rank (decode dst only) ----------------
__global__ void degree_kernel(const int* __restrict__ e32, int N, int E) {
    int e = blockIdx.x * blockDim.x + threadIdx.x;
    int ET = E + N;
    if (e >= ET) return;
    int d;
    if (e < E) d = g_is64 ? e32[2 * E + 2 * e] : e32[E + e];
    else       d = e - E;
    g_rank[e] = atomicAdd(&g_deg[d], 1);
}

// ---------------- 3-kernel scan: deg -> exclusive offsets ----------------
__global__ void scan_local(int N) {
    __shared__ int wsum[32];
    int t = threadIdx.x, lane = t & 31, wid = t >> 5;
    int i = blockIdx.x * 1024 + t;
    int v = (i < N) ? g_deg[i] : 0;
    int x = v;
    #pragma unroll
    for (int o = 1; o < 32; o <<= 1) {
        int y = __shfl_up_sync(0xffffffffu, x, o);
        if (lane >= o) x += y;
    }
    if (lane == 31) wsum[wid] = x;
    __syncthreads();
    if (wid == 0) {
        int w = wsum[lane];
        #pragma unroll
        for (int o = 1; o < 32; o <<= 1) {
            int y = __shfl_up_sync(0xffffffffu, w, o);
            if (lane >= o) w += y;
        }
        wsum[lane] = w;
    }
    __syncthreads();
    int ex = (wid ? wsum[wid - 1] : 0) + x - v;
    if (i < N) g_off[i] = ex;
    if (t == 1023) g_bsum[blockIdx.x] = wsum[31];
}

__global__ void scan_blocks(int nb) {
    int t = threadIdx.x, lane = t & 31, wid = t >> 5;
    __shared__ int w0tot;
    int v = (t < nb) ? g_bsum[t] : 0;
    int x = v;
    #pragma unroll
    for (int o = 1; o < 32; o <<= 1) {
        int y = __shfl_up_sync(0xffffffffu, x, o);
        if (lane >= o) x += y;
    }
    if (wid == 0 && lane == 31) w0tot = x;
    __syncthreads();
    int ex = x - v + (wid ? w0tot : 0);
    if (t < nb) g_boff[t] = ex;
}

__global__ void scan_add(int N, int ET) {
    int i = blockIdx.x * 1024 + threadIdx.x;
    if (i < N) g_off[i] += g_boff[blockIdx.x];
    if (i == 0) g_off[N] = ET;
}

// ---------------- edge pass 2: decode, exp(leakyrelu), scatter packed rec ----------------
__global__ void edge_pass2(const int* __restrict__ e32, int N, int E) {
    int e = blockIdx.x * blockDim.x + threadIdx.x;
    int ET = E + N;
    if (e >= ET) return;
    int s, d;
    if (e < E) {
        if (g_is64) { s = e32[2 * e]; d = e32[2 * E + 2 * e]; }
        else        { s = e32[e];     d = e32[E + e]; }
    } else {
        s = d = e - E;
    }
    float4 as = *(const float4*)&g_asrc[s * 4];
    float4 ad = *(const float4*)&g_adst[d * 4];
    float l0 = as.x + ad.x, l1 = as.y + ad.y, l2 = as.z + ad.z, l3 = as.w + ad.w;
    l0 = l0 > 0.f ? l0 : 0.2f * l0;
    l1 = l1 > 0.f ? l1 : 0.2f * l1;
    l2 = l2 > 0.f ? l2 : 0.2f * l2;
    l3 = l3 > 0.f ? l3 : 0.2f * l3;
    __half2 e01 = __floats2half2_rn(__expf(l0), __expf(l1));
    __half2 e23 = __floats2half2_rn(__expf(l2), __expf(l3));
    float4 rec;
    rec.x = __int_as_float(s);
    rec.y = __uint_as_float(*(const unsigned int*)&e01);
    rec.z = __uint_as_float(*(const unsigned int*)&e23);
    rec.w = 0.0f;
    int pos = g_off[d] + g_rank[e];
    g_pack[pos] = rec;
}

// ---------------- warp-per-dst-node aggregation; segsum computed in-loop ----------------
__global__ void aggregate_kernel(const float* __restrict__ bias,
                                 float* __restrict__ out, int N) {
    int gw = (blockIdx.x * blockDim.x + threadIdx.x) >> 5;
    int lane = threadIdx.x & 31;
    if (gw >= N) return;
    int beg = g_off[gw], end = g_off[gw + 1];
    float a00 = 0.f, a01 = 0.f, a10 = 0.f, a11 = 0.f;
    float a20 = 0.f, a21 = 0.f, a30 = 0.f, a31 = 0.f;
    float s0 = 0.f, s1 = 0.f, s2 = 0.f, s3 = 0.f;
    for (int j = beg; j < end; j++) {
        float4 rec = g_pack[j];
        int s = __float_as_int(rec.x);
        unsigned int u01 = __float_as_uint(rec.y);
        unsigned int u23 = __float_as_uint(rec.z);
        float2 w01 = __half22float2(*(const __half2*)&u01);
        float2 w23 = __half22float2(*(const __half2*)&u23);
        const __half2* xr = (const __half2*)(g_xh + s * HC);
        float2 v0 = __half22float2(xr[lane]);
        float2 v1 = __half22float2(xr[32 + lane]);
        float2 v2 = __half22float2(xr[64 + lane]);
        float2 v3 = __half22float2(xr[96 + lane]);
        a00 += w01.x * v0.x; a01 += w01.x * v0.y;
        a10 += w01.y * v1.x; a11 += w01.y * v1.y;
        a20 += w23.x * v2.x; a21 += w23.x * v2.y;
        a30 += w23.y * v3.x; a31 += w23.y * v3.y;
        s0 += w01.x; s1 += w01.y; s2 += w23.x; s3 += w23.y;
    }
    float n0 = 0.25f / (s0 + 1e-16f);
    float n1 = 0.25f / (s1 + 1e-16f);
    float n2 = 0.25f / (s2 + 1e-16f);
    float n3 = 0.25f / (s3 + 1e-16f);
    int c = 2 * lane;
    float o0 = a00 * n0 + a10 * n1 + a20 * n2 + a30 * n3 + bias[c];
    float o1 = a01 * n0 + a11 * n1 + a21 * n2 + a31 * n3 + bias[c + 1];
    *(float2*)&out[gw * 64 + c] = make_float2(o0, o1);
}

// ---------------- launch ----------------
extern "C" void kernel_launch(void* const* d_in, const int* in_sizes, int n_in,
                              void* d_out, int out_size) {
    const float* meta_x  = (const float*)d_in[0];
    const int*   edge32  = (const int*)d_in[1];
    const float* W       = (const float*)d_in[2];
    const float* att_src = (const float*)d_in[3];
    const float* att_dst = (const float*)d_in[4];
    const float* bias    = (const float*)d_in[5];
    float*       out     = (float*)d_out;

    int N  = in_sizes[0] / 64;
    int E  = in_sizes[1] / 2;
    int ET = E + N;
    int nb = (N + 1023) / 1024;

    detect_init_kernel<<<(N + 255) / 256, 256>>>(edge32, N);
    wh_kernel<<<16, 256>>>(W);
    gemm_mma_kernel<<<(N + 63) / 64, 512>>>(meta_x, att_src, att_dst, N);
    degree_kernel<<<(ET + 255) / 256, 256>>>(edge32, N, E);
    scan_local<<<nb, 1024>>>(N);
    scan_blocks<<<1, 64>>>(nb);
    scan_add<<<nb, 1024>>>(N, ET);
    edge_pass2<<<(ET + 255) / 256, 256>>>(edge32, N, E);
    aggregate_kernel<<<(N * 32 + 255) / 256, 256>>>(bias, out, N);
}

// round 10
// speedup vs baseline: 1.4267x; 1.0180x over previous
#include <cuda_runtime.h>
#include <cuda_fp16.h>
#include <cstdint>

// Problem constants (from reference): N=50000, DIM=64, HEADS=4, E=800000.
#define MAXN 50000
#define MAXE 800000
#define MAXET (MAXE + MAXN)
#define HC 256   // HEADS * DIM

// ---------------- scratch (static device globals; no allocation) ----------------
__device__ __align__(16) __half g_xh[MAXN * HC];      // [N, H, C] = x @ W  (fp16)
__device__ __align__(16) __half g_wh[64 * 256];       // fp16 copy of W
__device__ __align__(16) float g_asrc[MAXN * 4];      // [N, H]
__device__ __align__(16) float g_adst[MAXN * 4];      // [N, H]
__device__ int    g_deg[MAXN];
__device__ int    g_off[MAXN + 1];
__device__ int    g_bsum[64];
__device__ int    g_boff[64];
__device__ __align__(8) int g_rank[MAXET];            // within-dst rank of each edge
__device__ float4 g_pack[MAXET];                      // CSR rec: {src:int, exp01:h2, exp23:h2, pad}
__device__ int    g_is64;                             // 1 if edge buffer is int64

// ---------------- detect int64/int32 + init counters + W->fp16 (merged) ----------------
__global__ void detect_init_wh_kernel(const int* __restrict__ e32,
                                      const float* __restrict__ W, int N) {
    int i = blockIdx.x * blockDim.x + threadIdx.x;
    if (i < N) g_deg[i] = 0;
    if (blockIdx.x == 0) {
        __shared__ int s_any;
        if (threadIdx.x == 0) s_any = 0;
        __syncthreads();
        int any = 0;
        for (int k = threadIdx.x; k < 2048; k += blockDim.x)
            any |= e32[2 * k + 1];
        if (any) atomicOr(&s_any, 1);
        __syncthreads();
        if (threadIdx.x == 0) g_is64 = s_any ? 0 : 1;
    } else if (blockIdx.x <= 16) {
        int j = (blockIdx.x - 1) * 256 + threadIdx.x;   // 0..4095, 4 floats each
        float4 v = *(const float4*)&W[j * 4];
        *(__half2*)&g_wh[j * 4]     = __floats2half2_rn(v.x, v.y);
        *(__half2*)&g_wh[j * 4 + 2] = __floats2half2_rn(v.z, v.w);
    }
}

// ---------------- HMMA GEMM: g_xh[N,256] = fp16(X[N,64]) @ g_wh[64,256] ----------------
// 512 threads = 16 warps; block tile 64 rows x 256 cols.
// warp w: rows (w&3)*16, cols (w>>2)*64 (head w>>2). Fused a_src/a_dst epilogue.
__global__ void __launch_bounds__(512, 2) gemm_mma_kernel(const float* __restrict__ X,
                                                          const float* __restrict__ att_src,
                                                          const float* __restrict__ att_dst,
                                                          int N) {
    __shared__ __half sA[64][72];
    __shared__ __half sB[64][264];
    int row0 = blockIdx.x * 64;
    int t = threadIdx.x;

    #pragma unroll
    for (int i = t; i < 2048; i += 512) {
        int idx = i * 8;
        int k = idx >> 8, n = idx & 255;
        *(uint4*)&sB[k][n] = *(const uint4*)&g_wh[idx];
    }
    #pragma unroll
    for (int i = t; i < 1024; i += 512) {
        int idx = i * 4;
        int r = idx >> 6, k = idx & 63;
        int row = row0 + r;
        float4 v = (row < N) ? *(const float4*)&X[row * 64 + k]
                             : make_float4(0.f, 0.f, 0.f, 0.f);
        *(__half2*)&sA[r][k]     = __floats2half2_rn(v.x, v.y);
        *(__half2*)&sA[r][k + 2] = __floats2half2_rn(v.z, v.w);
    }
    __syncthreads();

    int w = t >> 5, lane = t & 31;
    int wr = (w & 3) * 16;
    int h  = w >> 2;
    int wc = h * 64;
    int m8 = lane >> 3, i8 = lane & 7;
    int rg = (m8 & 1) * 8 + i8;
    int cg = (m8 >> 1) * 8;

    float acc[8][4] = {};

    #pragma unroll
    for (int ki = 0; ki < 4; ki++) {
        uint32_t a0, a1, a2, a3;
        {
            uint32_t addr = (uint32_t)__cvta_generic_to_shared(
                &sA[wr + rg][ki * 16 + cg]);
            asm volatile("ldmatrix.sync.aligned.m8n8.x4.shared.b16 {%0,%1,%2,%3}, [%4];"
                         : "=r"(a0), "=r"(a1), "=r"(a2), "=r"(a3) : "r"(addr));
        }
        #pragma unroll
        for (int nj = 0; nj < 4; nj++) {
            uint32_t b0, b1, b2, b3;
            uint32_t addr = (uint32_t)__cvta_generic_to_shared(
                &sB[ki * 16 + rg][wc + nj * 16 + cg]);
            asm volatile("ldmatrix.sync.aligned.m8n8.x4.trans.shared.b16 {%0,%1,%2,%3}, [%4];"
                         : "=r"(b0), "=r"(b1), "=r"(b2), "=r"(b3) : "r"(addr));
            asm volatile(
                "mma.sync.aligned.m16n8k16.row.col.f32.f16.f16.f32 "
                "{%0,%1,%2,%3}, {%4,%5,%6,%7}, {%8,%9}, {%0,%1,%2,%3};"
                : "+f"(acc[nj * 2][0]), "+f"(acc[nj * 2][1]),
                  "+f"(acc[nj * 2][2]), "+f"(acc[nj * 2][3])
                : "r"(a0), "r"(a1), "r"(a2), "r"(a3), "r"(b0), "r"(b1));
            asm volatile(
                "mma.sync.aligned.m16n8k16.row.col.f32.f16.f16.f32 "
                "{%0,%1,%2,%3}, {%4,%5,%6,%7}, {%8,%9}, {%0,%1,%2,%3};"
                : "+f"(acc[nj * 2 + 1][0]), "+f"(acc[nj * 2 + 1][1]),
                  "+f"(acc[nj * 2 + 1][2]), "+f"(acc[nj * 2 + 1][3])
                : "r"(a0), "r"(a1), "r"(a2), "r"(a3), "r"(b2), "r"(b3));
        }
    }

    int rrow = lane >> 2, rcol = (lane & 3) * 2;
    int row = row0 + wr + rrow;
    float ps = 0.f, pd = 0.f, ps8 = 0.f, pd8 = 0.f;
    #pragma unroll
    for (int ni = 0; ni < 8; ni++) {
        int col = wc + ni * 8 + rcol;
        if (row < N)
            *(__half2*)&g_xh[row * HC + col] = __floats2half2_rn(acc[ni][0], acc[ni][1]);
        if (row + 8 < N)
            *(__half2*)&g_xh[(row + 8) * HC + col] = __floats2half2_rn(acc[ni][2], acc[ni][3]);
        float2 as2 = *(const float2*)&att_src[col];
        float2 ad2 = *(const float2*)&att_dst[col];
        ps  += acc[ni][0] * as2.x + acc[ni][1] * as2.y;
        pd  += acc[ni][0] * ad2.x + acc[ni][1] * ad2.y;
        ps8 += acc[ni][2] * as2.x + acc[ni][3] * as2.y;
        pd8 += acc[ni][2] * ad2.x + acc[ni][3] * ad2.y;
    }
    #pragma unroll
    for (int o = 1; o < 4; o <<= 1) {
        ps  += __shfl_xor_sync(0xffffffffu, ps,  o);
        pd  += __shfl_xor_sync(0xffffffffu, pd,  o);
        ps8 += __shfl_xor_sync(0xffffffffu, ps8, o);
        pd8 += __shfl_xor_sync(0xffffffffu, pd8, o);
    }
    if ((lane & 3) == 0) {
        if (row < N) {
            g_asrc[row * 4 + h] = ps;
            g_adst[row * 4 + h] = pd;
        }
        if (row + 8 < N) {
            g_asrc[(row + 8) * 4 + h] = ps8;
            g_adst[(row + 8) * 4 + h] = pd8;
        }
    }
}

// ---------------- degree + rank: 2 edges per thread (MLP=2) ----------------
__global__ void degree_kernel(const int* __restrict__ e32, int N, int E) {
    int p = blockIdx.x * blockDim.x + threadIdx.x;
    int ET = E + N;
    int e0 = 2 * p, e1 = 2 * p + 1;
    if (e0 >= ET) return;
    bool has1 = (e1 < ET);
    int d0, d1 = 0;
    if (e1 < E) {                      // both real edges (E even: no straddle)
        if (g_is64) {
            int4 v = *(const int4*)&e32[2 * E + 4 * p];
            d0 = v.x; d1 = v.z;
        } else {
            int2 v = *(const int2*)&e32[E + 2 * p];
            d0 = v.x; d1 = v.y;
        }
    } else if (e0 >= E) {              // both self loops
        d0 = e0 - E;
        d1 = e1 - E;
    } else {                           // mixed / tail (scalar fallback)
        d0 = (e0 < E) ? (g_is64 ? e32[2 * E + 2 * e0] : e32[E + e0]) : e0 - E;
        d1 = has1 ? ((e1 < E) ? (g_is64 ? e32[2 * E + 2 * e1] : e32[E + e1]) : e1 - E) : 0;
    }
    int r0 = atomicAdd(&g_deg[d0], 1);
    if (has1) {
        int r1 = atomicAdd(&g_deg[d1], 1);
        *(int2*)&g_rank[e0] = make_int2(r0, r1);
    } else {
        g_rank[e0] = r0;
    }
}

// ---------------- 3-kernel scan: deg -> exclusive offsets ----------------
__global__ void scan_local(int N) {
    __shared__ int wsum[32];
    int t = threadIdx.x, lane = t & 31, wid = t >> 5;
    int i = blockIdx.x * 1024 + t;
    int v = (i < N) ? g_deg[i] : 0;
    int x = v;
    #pragma unroll
    for (int o = 1; o < 32; o <<= 1) {
        int y = __shfl_up_sync(0xffffffffu, x, o);
        if (lane >= o) x += y;
    }
    if (lane == 31) wsum[wid] = x;
    __syncthreads();
    if (wid == 0) {
        int w = wsum[lane];
        #pragma unroll
        for (int o = 1; o < 32; o <<= 1) {
            int y = __shfl_up_sync(0xffffffffu, w, o);
            if (lane >= o) w += y;
        }
        wsum[lane] = w;
    }
    __syncthreads();
    int ex = (wid ? wsum[wid - 1] : 0) + x - v;
    if (i < N) g_off[i] = ex;
    if (t == 1023) g_bsum[blockIdx.x] = wsum[31];
}

__global__ void scan_blocks(int nb) {
    int t = threadIdx.x, lane = t & 31, wid = t >> 5;
    __shared__ int w0tot;
    int v = (t < nb) ? g_bsum[t] : 0;
    int x = v;
    #pragma unroll
    for (int o = 1; o < 32; o <<= 1) {
        int y = __shfl_up_sync(0xffffffffu, x, o);
        if (lane >= o) x += y;
    }
    if (wid == 0 && lane == 31) w0tot = x;
    __syncthreads();
    int ex = x - v + (wid ? w0tot : 0);
    if (t < nb) g_boff[t] = ex;
}

__global__ void scan_add(int N, int ET) {
    int i = blockIdx.x * 1024 + threadIdx.x;
    if (i < N) g_off[i] += g_boff[blockIdx.x];
    if (i == 0) g_off[N] = ET;
}

// ---------------- edge pass 2: 2 edges per thread (MLP), scatter packed recs ----------------
__device__ __forceinline__ float4 make_rec(int s, const float4& as, const float4& ad) {
    float l0 = as.x + ad.x, l1 = as.y + ad.y, l2 = as.z + ad.z, l3 = as.w + ad.w;
    l0 = l0 > 0.f ? l0 : 0.2f * l0;
    l1 = l1 > 0.f ? l1 : 0.2f * l1;
    l2 = l2 > 0.f ? l2 : 0.2f * l2;
    l3 = l3 > 0.f ? l3 : 0.2f * l3;
    __half2 e01 = __floats2half2_rn(__expf(l0), __expf(l1));
    __half2 e23 = __floats2half2_rn(__expf(l2), __expf(l3));
    float4 rec;
    rec.x = __int_as_float(s);
    rec.y = __uint_as_float(*(const unsigned int*)&e01);
    rec.z = __uint_as_float(*(const unsigned int*)&e23);
    rec.w = 0.0f;
    return rec;
}

__global__ void edge_pass2(const int* __restrict__ e32, int N, int E) {
    int p = blockIdx.x * blockDim.x + threadIdx.x;
    int ET = E + N;
    int e0 = 2 * p, e1 = 2 * p + 1;
    if (e0 >= ET) return;
    bool has1 = (e1 < ET);
    int s0, d0, s1 = 0, d1 = 0;
    if (e1 < E) {
        if (g_is64) {
            int4 vs = *(const int4*)&e32[4 * p];
            int4 vd = *(const int4*)&e32[2 * E + 4 * p];
            s0 = vs.x; s1 = vs.z; d0 = vd.x; d1 = vd.z;
        } else {
            int2 vs = *(const int2*)&e32[2 * p];
            int2 vd = *(const int2*)&e32[E + 2 * p];
            s0 = vs.x; s1 = vs.y; d0 = vd.x; d1 = vd.y;
        }
    } else if (e0 >= E) {
        s0 = d0 = e0 - E;
        s1 = d1 = e1 - E;
    } else {
        if (e0 < E) {
            s0 = g_is64 ? e32[2 * e0] : e32[e0];
            d0 = g_is64 ? e32[2 * E + 2 * e0] : e32[E + e0];
        } else { s0 = d0 = e0 - E; }
        if (has1) {
            if (e1 < E) {
                s1 = g_is64 ? e32[2 * e1] : e32[e1];
                d1 = g_is64 ? e32[2 * E + 2 * e1] : e32[E + e1];
            } else { s1 = d1 = e1 - E; }
        }
    }
    // independent gathers (MLP up to 4)
    float4 as0 = *(const float4*)&g_asrc[s0 * 4];
    float4 ad0 = *(const float4*)&g_adst[d0 * 4];
    float4 as1, ad1;
    if (has1) {
        as1 = *(const float4*)&g_asrc[s1 * 4];
        ad1 = *(const float4*)&g_adst[d1 * 4];
    }
    int2 rk = has1 ? *(const int2*)&g_rank[e0] : make_int2(g_rank[e0], 0);
    float4 rec0 = make_rec(s0, as0, ad0);
    g_pack[g_off[d0] + rk.x] = rec0;
    if (has1) {
        float4 rec1 = make_rec(s1, as1, ad1);
        g_pack[g_off[d1] + rk.y] = rec1;
    }
}

// ---------------- warp-per-dst-node aggregation; segsum computed in-loop ----------------
__global__ void aggregate_kernel(const float* __restrict__ bias,
                                 float* __restrict__ out, int N) {
    int gw = (blockIdx.x * blockDim.x + threadIdx.x) >> 5;
    int lane = threadIdx.x & 31;
    if (gw >= N) return;
    int beg = g_off[gw], end = g_off[gw + 1];
    float a00 = 0.f, a01 = 0.f, a10 = 0.f, a11 = 0.f;
    float a20 = 0.f, a21 = 0.f, a30 = 0.f, a31 = 0.f;
    float s0 = 0.f, s1 = 0.f, s2 = 0.f, s3 = 0.f;
    for (int j = beg; j < end; j++) {
        float4 rec = g_pack[j];
        int s = __float_as_int(rec.x);
        unsigned int u01 = __float_as_uint(rec.y);
        unsigned int u23 = __float_as_uint(rec.z);
        float2 w01 = __half22float2(*(const __half2*)&u01);
        float2 w23 = __half22float2(*(const __half2*)&u23);
        const __half2* xr = (const __half2*)(g_xh + s * HC);
        float2 v0 = __half22float2(xr[lane]);
        float2 v1 = __half22float2(xr[32 + lane]);
        float2 v2 = __half22float2(xr[64 + lane]);
        float2 v3 = __half22float2(xr[96 + lane]);
        a00 += w01.x * v0.x; a01 += w01.x * v0.y;
        a10 += w01.y * v1.x; a11 += w01.y * v1.y;
        a20 += w23.x * v2.x; a21 += w23.x * v2.y;
        a30 += w23.y * v3.x; a31 += w23.y * v3.y;
        s0 += w01.x; s1 += w01.y; s2 += w23.x; s3 += w23.y;
    }
    float n0 = 0.25f / (s0 + 1e-16f);
    float n1 = 0.25f / (s1 + 1e-16f);
    float n2 = 0.25f / (s2 + 1e-16f);
    float n3 = 0.25f / (s3 + 1e-16f);
    int c = 2 * lane;
    float o0 = a00 * n0 + a10 * n1 + a20 * n2 + a30 * n3 + bias[c];
    float o1 = a01 * n0 + a11 * n1 + a21 * n2 + a31 * n3 + bias[c + 1];
    *(float2*)&out[gw * 64 + c] = make_float2(o0, o1);
}

// ---------------- launch ----------------
extern "C" void kernel_launch(void* const* d_in, const int* in_sizes, int n_in,
                              void* d_out, int out_size) {
    const float* meta_x  = (const float*)d_in[0];
    const int*   edge32  = (const int*)d_in[1];
    const float* W       = (const float*)d_in[2];
    const float* att_src = (const float*)d_in[3];
    const float* att_dst = (const float*)d_in[4];
    const float* bias    = (const float*)d_in[5];
    float*       out     = (float*)d_out;

    int N  = in_sizes[0] / 64;
    int E  = in_sizes[1] / 2;
    int ET = E + N;
    int nb = (N + 1023) / 1024;
    int np = (ET + 1) / 2;                 // edge pairs

    detect_init_wh_kernel<<<(N + 255) / 256, 256>>>(edge32, W, N);
    gemm_mma_kernel<<<(N + 63) / 64, 512>>>(meta_x, att_src, att_dst, N);
    degree_kernel<<<(np + 255) / 256, 256>>>(edge32, N, E);
    scan_local<<<nb, 1024>>>(N);
    scan_blocks<<<1, 64>>>(nb);
    scan_add<<<nb, 1024>>>(N, ET);
    edge_pass2<<<(np + 255) / 256, 256>>>(edge32, N, E);
    aggregate_kernel<<<(N * 32 + 255) / 256, 256>>>(bias, out, N);
}

// round 11
// speedup vs baseline: 1.4562x; 1.0207x over previous
#include <cuda_runtime.h>
#include <cuda_fp16.h>
#include <cstdint>

// Problem constants (from reference): N=50000, DIM=64, HEADS=4, E=800000.
#define MAXN 50000
#define MAXE 800000
#define MAXET (MAXE + MAXN)
#define HC 256   // HEADS * DIM

// ---------------- scratch (static device globals; no allocation) ----------------
__device__ __align__(16) __half g_xh[MAXN * HC];      // [N, H, C] = x @ W  (fp16)
__device__ __align__(16) __half g_wh[64 * 256];       // fp16 copy of W
__device__ __align__(16) float g_asrc[MAXN * 4];      // [N, H]
__device__ __align__(16) float g_adst[MAXN * 4];      // [N, H]
__device__ int    g_deg[MAXN];
__device__ int    g_off[MAXN + 1];
__device__ int    g_flag[64];                         // lookback: 0=unready else agg+1
__device__ __align__(8) int g_rank[MAXET];            // within-dst rank of each edge
__device__ float4 g_pack[MAXET];                      // CSR rec: {src:int, exp01:h2, exp23:h2, pad}
__device__ int    g_is64;                             // 1 if edge buffer is int64

// ---------------- detect int64/int32 + init counters/flags + W->fp16 (merged) ----------------
__global__ void detect_init_wh_kernel(const int* __restrict__ e32,
                                      const float* __restrict__ W, int N) {
    int i = blockIdx.x * blockDim.x + threadIdx.x;
    if (i < N) g_deg[i] = 0;
    if (i < 64) g_flag[i] = 0;
    if (blockIdx.x == 0) {
        __shared__ int s_any;
        if (threadIdx.x == 0) s_any = 0;
        __syncthreads();
        int any = 0;
        for (int k = threadIdx.x; k < 2048; k += blockDim.x)
            any |= e32[2 * k + 1];
        if (any) atomicOr(&s_any, 1);
        __syncthreads();
        if (threadIdx.x == 0) g_is64 = s_any ? 0 : 1;
    } else if (blockIdx.x <= 16) {
        int j = (blockIdx.x - 1) * 256 + threadIdx.x;   // 0..4095, 4 floats each
        float4 v = *(const float4*)&W[j * 4];
        *(__half2*)&g_wh[j * 4]     = __floats2half2_rn(v.x, v.y);
        *(__half2*)&g_wh[j * 4 + 2] = __floats2half2_rn(v.z, v.w);
    }
}

// ---------------- degree role: 512 threads, 2 edges per thread (MLP=2) ----------------
__device__ __forceinline__ void degree_role(const int* __restrict__ e32,
                                            int N, int E, int blk) {
    int p = blk * 512 + threadIdx.x;
    int ET = E + N;
    int e0 = 2 * p, e1 = 2 * p + 1;
    if (e0 >= ET) return;
    bool has1 = (e1 < ET);
    int d0, d1 = 0;
    if (e1 < E) {                      // both real edges (E even: no straddle)
        if (g_is64) {
            int4 v = *(const int4*)&e32[2 * E + 4 * p];
            d0 = v.x; d1 = v.z;
        } else {
            int2 v = *(const int2*)&e32[E + 2 * p];
            d0 = v.x; d1 = v.y;
        }
    } else if (e0 >= E) {              // both self loops
        d0 = e0 - E;
        d1 = e1 - E;
    } else {                           // mixed / tail
        d0 = (e0 < E) ? (g_is64 ? e32[2 * E + 2 * e0] : e32[E + e0]) : e0 - E;
        d1 = has1 ? ((e1 < E) ? (g_is64 ? e32[2 * E + 2 * e1] : e32[E + e1]) : e1 - E) : 0;
    }
    int r0 = atomicAdd(&g_deg[d0], 1);
    if (has1) {
        int r1 = atomicAdd(&g_deg[d1], 1);
        *(int2*)&g_rank[e0] = make_int2(r0, r1);
    } else {
        g_rank[e0] = r0;
    }
}

// ---------------- fused: degree blocks + HMMA GEMM blocks in one launch ----------------
// blocks [0, degBlocks): degree histogram. blocks [degBlocks, ...): GEMM tile.
// GEMM: 512 thr = 16 warps; tile 64 rows x 256 cols; warp w: rows (w&3)*16, head w>>2.
// Fused a_src/a_dst epilogue from fp32 accumulators.
__global__ void __launch_bounds__(512, 2) gemm_degree_kernel(
        const float* __restrict__ X,
        const float* __restrict__ att_src,
        const float* __restrict__ att_dst,
        const int* __restrict__ e32,
        int N, int E, int degBlocks) {
    __shared__ __half sA[64][72];
    __shared__ __half sB[64][264];

    if (blockIdx.x < degBlocks) {
        degree_role(e32, N, E, blockIdx.x);
        return;
    }
    int row0 = (blockIdx.x - degBlocks) * 64;
    int t = threadIdx.x;

    #pragma unroll
    for (int i = t; i < 2048; i += 512) {
        int idx = i * 8;
        int k = idx >> 8, n = idx & 255;
        *(uint4*)&sB[k][n] = *(const uint4*)&g_wh[idx];
    }
    #pragma unroll
    for (int i = t; i < 1024; i += 512) {
        int idx = i * 4;
        int r = idx >> 6, k = idx & 63;
        int row = row0 + r;
        float4 v = (row < N) ? *(const float4*)&X[row * 64 + k]
                             : make_float4(0.f, 0.f, 0.f, 0.f);
        *(__half2*)&sA[r][k]     = __floats2half2_rn(v.x, v.y);
        *(__half2*)&sA[r][k + 2] = __floats2half2_rn(v.z, v.w);
    }
    __syncthreads();

    int w = t >> 5, lane = t & 31;
    int wr = (w & 3) * 16;
    int h  = w >> 2;
    int wc = h * 64;
    int m8 = lane >> 3, i8 = lane & 7;
    int rg = (m8 & 1) * 8 + i8;
    int cg = (m8 >> 1) * 8;

    float acc[8][4] = {};

    #pragma unroll
    for (int ki = 0; ki < 4; ki++) {
        uint32_t a0, a1, a2, a3;
        {
            uint32_t addr = (uint32_t)__cvta_generic_to_shared(
                &sA[wr + rg][ki * 16 + cg]);
            asm volatile("ldmatrix.sync.aligned.m8n8.x4.shared.b16 {%0,%1,%2,%3}, [%4];"
                         : "=r"(a0), "=r"(a1), "=r"(a2), "=r"(a3) : "r"(addr));
        }
        #pragma unroll
        for (int nj = 0; nj < 4; nj++) {
            uint32_t b0, b1, b2, b3;
            uint32_t addr = (uint32_t)__cvta_generic_to_shared(
                &sB[ki * 16 + rg][wc + nj * 16 + cg]);
            asm volatile("ldmatrix.sync.aligned.m8n8.x4.trans.shared.b16 {%0,%1,%2,%3}, [%4];"
                         : "=r"(b0), "=r"(b1), "=r"(b2), "=r"(b3) : "r"(addr));
            asm volatile(
                "mma.sync.aligned.m16n8k16.row.col.f32.f16.f16.f32 "
                "{%0,%1,%2,%3}, {%4,%5,%6,%7}, {%8,%9}, {%0,%1,%2,%3};"
                : "+f"(acc[nj * 2][0]), "+f"(acc[nj * 2][1]),
                  "+f"(acc[nj * 2][2]), "+f"(acc[nj * 2][3])
                : "r"(a0), "r"(a1), "r"(a2), "r"(a3), "r"(b0), "r"(b1));
            asm volatile(
                "mma.sync.aligned.m16n8k16.row.col.f32.f16.f16.f32 "
                "{%0,%1,%2,%3}, {%4,%5,%6,%7}, {%8,%9}, {%0,%1,%2,%3};"
                : "+f"(acc[nj * 2 + 1][0]), "+f"(acc[nj * 2 + 1][1]),
                  "+f"(acc[nj * 2 + 1][2]), "+f"(acc[nj * 2 + 1][3])
                : "r"(a0), "r"(a1), "r"(a2), "r"(a3), "r"(b2), "r"(b3));
        }
    }

    int rrow = lane >> 2, rcol = (lane & 3) * 2;
    int row = row0 + wr + rrow;
    float ps = 0.f, pd = 0.f, ps8 = 0.f, pd8 = 0.f;
    #pragma unroll
    for (int ni = 0; ni < 8; ni++) {
        int col = wc + ni * 8 + rcol;
        if (row < N)
            *(__half2*)&g_xh[row * HC + col] = __floats2half2_rn(acc[ni][0], acc[ni][1]);
        if (row + 8 < N)
            *(__half2*)&g_xh[(row + 8) * HC + col] = __floats2half2_rn(acc[ni][2], acc[ni][3]);
        float2 as2 = *(const float2*)&att_src[col];
        float2 ad2 = *(const float2*)&att_dst[col];
        ps  += acc[ni][0] * as2.x + acc[ni][1] * as2.y;
        pd  += acc[ni][0] * ad2.x + acc[ni][1] * ad2.y;
        ps8 += acc[ni][2] * as2.x + acc[ni][3] * as2.y;
        pd8 += acc[ni][2] * ad2.x + acc[ni][3] * ad2.y;
    }
    #pragma unroll
    for (int o = 1; o < 4; o <<= 1) {
        ps  += __shfl_xor_sync(0xffffffffu, ps,  o);
        pd  += __shfl_xor_sync(0xffffffffu, pd,  o);
        ps8 += __shfl_xor_sync(0xffffffffu, ps8, o);
        pd8 += __shfl_xor_sync(0xffffffffu, pd8, o);
    }
    if ((lane & 3) == 0) {
        if (row < N) {
            g_asrc[row * 4 + h] = ps;
            g_adst[row * 4 + h] = pd;
        }
        if (row + 8 < N) {
            g_asrc[(row + 8) * 4 + h] = ps8;
            g_adst[(row + 8) * 4 + h] = pd8;
        }
    }
}

// ---------------- single-pass decoupled-lookback scan: deg -> exclusive g_off ----------------
// nb <= 49 blocks, all co-resident (148 SMs) -> polling cannot deadlock.
__global__ void scan_lookback(int N, int ET, int nb) {
    __shared__ int wsum[32];
    __shared__ int s_prev;
    int b = blockIdx.x;
    int t = threadIdx.x, lane = t & 31, wid = t >> 5;
    int i = b * 1024 + t;
    int v = (i < N) ? g_deg[i] : 0;
    int x = v;
    #pragma unroll
    for (int o = 1; o < 32; o <<= 1) {
        int y = __shfl_up_sync(0xffffffffu, x, o);
        if (lane >= o) x += y;
    }
    if (lane == 31) wsum[wid] = x;
    if (t == 0) s_prev = 0;
    __syncthreads();
    if (wid == 0) {
        int w = wsum[lane];
        #pragma unroll
        for (int o = 1; o < 32; o <<= 1) {
            int y = __shfl_up_sync(0xffffffffu, w, o);
            if (lane >= o) w += y;
        }
        wsum[lane] = w;
    }
    __syncthreads();
    int agg = wsum[31];                       // block total
    if (t == 0) atomicExch(&g_flag[b], agg + 1);   // publish (0 = unready)
    // lookback: thread t (< b) polls predecessor t's aggregate
    if (t < b) {
        int f;
        do { f = atomicAdd(&g_flag[t], 0); } while (f == 0);
        atomicAdd(&s_prev, f - 1);
    }
    __syncthreads();
    int base = s_prev;
    int ex = (wid ? wsum[wid - 1] : 0) + x - v;
    if (i < N) g_off[i] = base + ex;
    if (b == nb - 1 && t == 0) g_off[N] = ET;
}

// ---------------- edge pass 2: 2 edges per thread, scatter packed recs ----------------
__device__ __forceinline__ float4 make_rec(int s, const float4& as, const float4& ad) {
    float l0 = as.x + ad.x, l1 = as.y + ad.y, l2 = as.z + ad.z, l3 = as.w + ad.w;
    l0 = l0 > 0.f ? l0 : 0.2f * l0;
    l1 = l1 > 0.f ? l1 : 0.2f * l1;
    l2 = l2 > 0.f ? l2 : 0.2f * l2;
    l3 = l3 > 0.f ? l3 : 0.2f * l3;
    __half2 e01 = __floats2half2_rn(__expf(l0), __expf(l1));
    __half2 e23 = __floats2half2_rn(__expf(l2), __expf(l3));
    float4 rec;
    rec.x = __int_as_float(s);
    rec.y = __uint_as_float(*(const unsigned int*)&e01);
    rec.z = __uint_as_float(*(const unsigned int*)&e23);
    rec.w = 0.0f;
    return rec;
}

__global__ void edge_pass2(const int* __restrict__ e32, int N, int E) {
    int p = blockIdx.x * blockDim.x + threadIdx.x;
    int ET = E + N;
    int e0 = 2 * p, e1 = 2 * p + 1;
    if (e0 >= ET) return;
    bool has1 = (e1 < ET);
    int s0, d0, s1 = 0, d1 = 0;
    if (e1 < E) {
        if (g_is64) {
            int4 vs = *(const int4*)&e32[4 * p];
            int4 vd = *(const int4*)&e32[2 * E + 4 * p];
            s0 = vs.x; s1 = vs.z; d0 = vd.x; d1 = vd.z;
        } else {
            int2 vs = *(const int2*)&e32[2 * p];
            int2 vd = *(const int2*)&e32[E + 2 * p];
            s0 = vs.x; s1 = vs.y; d0 = vd.x; d1 = vd.y;
        }
    } else if (e0 >= E) {
        s0 = d0 = e0 - E;
        s1 = d1 = e1 - E;
    } else {
        if (e0 < E) {
            s0 = g_is64 ? e32[2 * e0] : e32[e0];
            d0 = g_is64 ? e32[2 * E + 2 * e0] : e32[E + e0];
        } else { s0 = d0 = e0 - E; }
        if (has1) {
            if (e1 < E) {
                s1 = g_is64 ? e32[2 * e1] : e32[e1];
                d1 = g_is64 ? e32[2 * E + 2 * e1] : e32[E + e1];
            } else { s1 = d1 = e1 - E; }
        }
    }
    float4 as0 = *(const float4*)&g_asrc[s0 * 4];
    float4 ad0 = *(const float4*)&g_adst[d0 * 4];
    float4 as1, ad1;
    if (has1) {
        as1 = *(const float4*)&g_asrc[s1 * 4];
        ad1 = *(const float4*)&g_adst[d1 * 4];
    }
    int2 rk = has1 ? *(const int2*)&g_rank[e0] : make_int2(g_rank[e0], 0);
    float4 rec0 = make_rec(s0, as0, ad0);
    g_pack[g_off[d0] + rk.x] = rec0;
    if (has1) {
        float4 rec1 = make_rec(s1, as1, ad1);
        g_pack[g_off[d1] + rk.y] = rec1;
    }
}

// ---------------- warp-per-dst-node aggregation; segsum computed in-loop ----------------
__global__ void aggregate_kernel(const float* __restrict__ bias,
                                 float* __restrict__ out, int N) {
    int gw = (blockIdx.x * blockDim.x + threadIdx.x) >> 5;
    int lane = threadIdx.x & 31;
    if (gw >= N) return;
    int beg = g_off[gw], end = g_off[gw + 1];
    float a00 = 0.f, a01 = 0.f, a10 = 0.f, a11 = 0.f;
    float a20 = 0.f, a21 = 0.f, a30 = 0.f, a31 = 0.f;
    float s0 = 0.f, s1 = 0.f, s2 = 0.f, s3 = 0.f;
    for (int j = beg; j < end; j++) {
        float4 rec = g_pack[j];
        int s = __float_as_int(rec.x);
        unsigned int u01 = __float_as_uint(rec.y);
        unsigned int u23 = __float_as_uint(rec.z);
        float2 w01 = __half22float2(*(const __half2*)&u01);
        float2 w23 = __half22float2(*(const __half2*)&u23);
        const __half2* xr = (const __half2*)(g_xh + s * HC);
        float2 v0 = __half22float2(xr[lane]);
        float2 v1 = __half22float2(xr[32 + lane]);
        float2 v2 = __half22float2(xr[64 + lane]);
        float2 v3 = __half22float2(xr[96 + lane]);
        a00 += w01.x * v0.x; a01 += w01.x * v0.y;
        a10 += w01.y * v1.x; a11 += w01.y * v1.y;
        a20 += w23.x * v2.x; a21 += w23.x * v2.y;
        a30 += w23.y * v3.x; a31 += w23.y * v3.y;
        s0 += w01.x; s1 += w01.y; s2 += w23.x; s3 += w23.y;
    }
    float n0 = 0.25f / (s0 + 1e-16f);
    float n1 = 0.25f / (s1 + 1e-16f);
    float n2 = 0.25f / (s2 + 1e-16f);
    float n3 = 0.25f / (s3 + 1e-16f);
    int c = 2 * lane;
    float o0 = a00 * n0 + a10 * n1 + a20 * n2 + a30 * n3 + bias[c];
    float o1 = a01 * n0 + a11 * n1 + a21 * n2 + a31 * n3 + bias[c + 1];
    *(float2*)&out[gw * 64 + c] = make_float2(o0, o1);
}

// ---------------- launch ----------------
extern "C" void kernel_launch(void* const* d_in, const int* in_sizes, int n_in,
                              void* d_out, int out_size) {
    const float* meta_x  = (const float*)d_in[0];
    const int*   edge32  = (const int*)d_in[1];
    const float* W       = (const float*)d_in[2];
    const float* att_src = (const float*)d_in[3];
    const float* att_dst = (const float*)d_in[4];
    const float* bias    = (const float*)d_in[5];
    float*       out     = (float*)d_out;

    int N  = in_sizes[0] / 64;
    int E  = in_sizes[1] / 2;
    int ET = E + N;
    int nb = (N + 1023) / 1024;
    int np = (ET + 1) / 2;                       // edge pairs
    int degBlocks  = (np + 511) / 512;           // degree role blocks (512 thr)
    int gemmBlocks = (N + 63) / 64;

    detect_init_wh_kernel<<<(N + 255) / 256, 256>>>(edge32, W, N);
    gemm_degree_kernel<<<degBlocks + gemmBlocks, 512>>>(meta_x, att_src, att_dst,
                                                        edge32, N, E, degBlocks);
    scan_lookback<<<nb, 1024>>>(N, ET, nb);
    edge_pass2<<<(np + 255) / 256, 256>>>(edge32, N, E);
    aggregate_kernel<<<(N * 32 + 255) / 256, 256>>>(bias, out, N);
}

// round 12
// speedup vs baseline: 1.4973x; 1.0282x over previous
#include <cuda_runtime.h>
#include <cuda_fp16.h>
#include <cstdint>

// Problem constants (from reference): N=50000, DIM=64, HEADS=4, E=800000.
#define MAXN 50000
#define MAXE 800000
#define MAXET (MAXE + MAXN)
#define HC 256   // HEADS * DIM

// ---------------- scratch (static device globals; no allocation) ----------------
__device__ __align__(16) __half g_xh[MAXN * HC];      // [N, H, C] = x @ W  (fp16)
__device__ __align__(16) __half g_wh[64 * 256];       // fp16 copy of W
__device__ __align__(16) float g_asrc[MAXN * 4];      // [N, H]
__device__ __align__(16) float g_adst[MAXN * 4];      // [N, H]
__device__ int    g_deg[MAXN];
__device__ int    g_off[MAXN + 1];
__device__ int    g_flag[64];                         // lookback: 0=unready else agg+1
__device__ __align__(8) int g_rank[MAXET];            // within-dst rank of each edge
__device__ float4 g_pack[MAXET];                      // CSR rec: {src:int, exp01:h2, exp23:h2, pad}
__device__ int    g_is64;                             // 1 if edge buffer is int64

// ---------------- detect int64/int32 + init counters/flags + W->fp16 (merged) ----------------
__global__ void detect_init_wh_kernel(const int* __restrict__ e32,
                                      const float* __restrict__ W, int N) {
    int i = blockIdx.x * blockDim.x + threadIdx.x;
    if (i < N) g_deg[i] = 0;
    if (i < 64) g_flag[i] = 0;
    if (blockIdx.x == 0) {
        __shared__ int s_any;
        if (threadIdx.x == 0) s_any = 0;
        __syncthreads();
        int any = 0;
        for (int k = threadIdx.x; k < 2048; k += blockDim.x)
            any |= e32[2 * k + 1];
        if (any) atomicOr(&s_any, 1);
        __syncthreads();
        if (threadIdx.x == 0) g_is64 = s_any ? 0 : 1;
    } else if (blockIdx.x <= 16) {
        int j = (blockIdx.x - 1) * 256 + threadIdx.x;   // 0..4095, 4 floats each
        float4 v = *(const float4*)&W[j * 4];
        *(__half2*)&g_wh[j * 4]     = __floats2half2_rn(v.x, v.y);
        *(__half2*)&g_wh[j * 4 + 2] = __floats2half2_rn(v.z, v.w);
    }
}

// ---------------- degree role: 512 threads, 2 edges per thread (MLP=2) ----------------
__device__ __forceinline__ void degree_role(const int* __restrict__ e32,
                                            int N, int E, int blk) {
    int p = blk * 512 + threadIdx.x;
    int ET = E + N;
    int e0 = 2 * p, e1 = 2 * p + 1;
    if (e0 >= ET) return;
    bool has1 = (e1 < ET);
    int d0, d1 = 0;
    if (e1 < E) {                      // both real edges (E even: no straddle)
        if (g_is64) {
            int4 v = *(const int4*)&e32[2 * E + 4 * p];
            d0 = v.x; d1 = v.z;
        } else {
            int2 v = *(const int2*)&e32[E + 2 * p];
            d0 = v.x; d1 = v.y;
        }
    } else if (e0 >= E) {              // both self loops
        d0 = e0 - E;
        d1 = e1 - E;
    } else {                           // mixed / tail
        d0 = (e0 < E) ? (g_is64 ? e32[2 * E + 2 * e0] : e32[E + e0]) : e0 - E;
        d1 = has1 ? ((e1 < E) ? (g_is64 ? e32[2 * E + 2 * e1] : e32[E + e1]) : e1 - E) : 0;
    }
    int r0 = atomicAdd(&g_deg[d0], 1);
    if (has1) {
        int r1 = atomicAdd(&g_deg[d1], 1);
        *(int2*)&g_rank[e0] = make_int2(r0, r1);
    } else {
        g_rank[e0] = r0;
    }
}

// ---------------- fused + INTERLEAVED: degree blocks + HMMA GEMM blocks ----------------
// Even/odd blockIdx alternates roles over the common range so each wave co-hosts
// both workloads (atomics overlap tensor work). Excess blocks take the longer role.
__global__ void __launch_bounds__(512, 2) gemm_degree_kernel(
        const float* __restrict__ X,
        const float* __restrict__ att_src,
        const float* __restrict__ att_dst,
        const int* __restrict__ e32,
        int N, int E, int degBlocks, int gemmBlocks) {
    __shared__ __half sA[64][72];
    __shared__ __half sB[64][264];

    int b = blockIdx.x;
    int mn = degBlocks < gemmBlocks ? degBlocks : gemmBlocks;
    int nI = 2 * mn;
    bool isDeg;
    int idx;
    if (b < nI) { isDeg = (b & 1) == 0; idx = b >> 1; }
    else        { isDeg = degBlocks > gemmBlocks; idx = mn + (b - nI); }

    if (isDeg) {
        degree_role(e32, N, E, idx);
        return;
    }
    int row0 = idx * 64;
    int t = threadIdx.x;

    #pragma unroll
    for (int i = t; i < 2048; i += 512) {
        int idx2 = i * 8;
        int k = idx2 >> 8, n = idx2 & 255;
        *(uint4*)&sB[k][n] = *(const uint4*)&g_wh[idx2];
    }
    #pragma unroll
    for (int i = t; i < 1024; i += 512) {
        int idx2 = i * 4;
        int r = idx2 >> 6, k = idx2 & 63;
        int row = row0 + r;
        float4 v = (row < N) ? *(const float4*)&X[row * 64 + k]
                             : make_float4(0.f, 0.f, 0.f, 0.f);
        *(__half2*)&sA[r][k]     = __floats2half2_rn(v.x, v.y);
        *(__half2*)&sA[r][k + 2] = __floats2half2_rn(v.z, v.w);
    }
    __syncthreads();

    int w = t >> 5, lane = t & 31;
    int wr = (w & 3) * 16;
    int h  = w >> 2;
    int wc = h * 64;
    int m8 = lane >> 3, i8 = lane & 7;
    int rg = (m8 & 1) * 8 + i8;
    int cg = (m8 >> 1) * 8;

    float acc[8][4] = {};

    #pragma unroll
    for (int ki = 0; ki < 4; ki++) {
        uint32_t a0, a1, a2, a3;
        {
            uint32_t addr = (uint32_t)__cvta_generic_to_shared(
                &sA[wr + rg][ki * 16 + cg]);
            asm volatile("ldmatrix.sync.aligned.m8n8.x4.shared.b16 {%0,%1,%2,%3}, [%4];"
                         : "=r"(a0), "=r"(a1), "=r"(a2), "=r"(a3) : "r"(addr));
        }
        #pragma unroll
        for (int nj = 0; nj < 4; nj++) {
            uint32_t b0, b1, b2, b3;
            uint32_t addr = (uint32_t)__cvta_generic_to_shared(
                &sB[ki * 16 + rg][wc + nj * 16 + cg]);
            asm volatile("ldmatrix.sync.aligned.m8n8.x4.trans.shared.b16 {%0,%1,%2,%3}, [%4];"
                         : "=r"(b0), "=r"(b1), "=r"(b2), "=r"(b3) : "r"(addr));
            asm volatile(
                "mma.sync.aligned.m16n8k16.row.col.f32.f16.f16.f32 "
                "{%0,%1,%2,%3}, {%4,%5,%6,%7}, {%8,%9}, {%0,%1,%2,%3};"
                : "+f"(acc[nj * 2][0]), "+f"(acc[nj * 2][1]),
                  "+f"(acc[nj * 2][2]), "+f"(acc[nj * 2][3])
                : "r"(a0), "r"(a1), "r"(a2), "r"(a3), "r"(b0), "r"(b1));
            asm volatile(
                "mma.sync.aligned.m16n8k16.row.col.f32.f16.f16.f32 "
                "{%0,%1,%2,%3}, {%4,%5,%6,%7}, {%8,%9}, {%0,%1,%2,%3};"
                : "+f"(acc[nj * 2 + 1][0]), "+f"(acc[nj * 2 + 1][1]),
                  "+f"(acc[nj * 2 + 1][2]), "+f"(acc[nj * 2 + 1][3])
                : "r"(a0), "r"(a1), "r"(a2), "r"(a3), "r"(b2), "r"(b3));
        }
    }

    int rrow = lane >> 2, rcol = (lane & 3) * 2;
    int row = row0 + wr + rrow;
    float ps = 0.f, pd = 0.f, ps8 = 0.f, pd8 = 0.f;
    #pragma unroll
    for (int ni = 0; ni < 8; ni++) {
        int col = wc + ni * 8 + rcol;
        if (row < N)
            *(__half2*)&g_xh[row * HC + col] = __floats2half2_rn(acc[ni][0], acc[ni][1]);
        if (row + 8 < N)
            *(__half2*)&g_xh[(row + 8) * HC + col] = __floats2half2_rn(acc[ni][2], acc[ni][3]);
        float2 as2 = *(const float2*)&att_src[col];
        float2 ad2 = *(const float2*)&att_dst[col];
        ps  += acc[ni][0] * as2.x + acc[ni][1] * as2.y;
        pd  += acc[ni][0] * ad2.x + acc[ni][1] * ad2.y;
        ps8 += acc[ni][2] * as2.x + acc[ni][3] * as2.y;
        pd8 += acc[ni][2] * ad2.x + acc[ni][3] * ad2.y;
    }
    #pragma unroll
    for (int o = 1; o < 4; o <<= 1) {
        ps  += __shfl_xor_sync(0xffffffffu, ps,  o);
        pd  += __shfl_xor_sync(0xffffffffu, pd,  o);
        ps8 += __shfl_xor_sync(0xffffffffu, ps8, o);
        pd8 += __shfl_xor_sync(0xffffffffu, pd8, o);
    }
    if ((lane & 3) == 0) {
        if (row < N) {
            g_asrc[row * 4 + h] = ps;
            g_adst[row * 4 + h] = pd;
        }
        if (row + 8 < N) {
            g_asrc[(row + 8) * 4 + h] = ps8;
            g_adst[(row + 8) * 4 + h] = pd8;
        }
    }
}

// ---------------- single-pass decoupled-lookback scan: deg -> exclusive g_off ----------------
__global__ void scan_lookback(int N, int ET, int nb) {
    __shared__ int wsum[32];
    __shared__ int s_prev;
    int b = blockIdx.x;
    int t = threadIdx.x, lane = t & 31, wid = t >> 5;
    int i = b * 1024 + t;
    int v = (i < N) ? g_deg[i] : 0;
    int x = v;
    #pragma unroll
    for (int o = 1; o < 32; o <<= 1) {
        int y = __shfl_up_sync(0xffffffffu, x, o);
        if (lane >= o) x += y;
    }
    if (lane == 31) wsum[wid] = x;
    if (t == 0) s_prev = 0;
    __syncthreads();
    if (wid == 0) {
        int w = wsum[lane];
        #pragma unroll
        for (int o = 1; o < 32; o <<= 1) {
            int y = __shfl_up_sync(0xffffffffu, w, o);
            if (lane >= o) w += y;
        }
        wsum[lane] = w;
    }
    __syncthreads();
    int agg = wsum[31];
    if (t == 0) atomicExch(&g_flag[b], agg + 1);
    if (t < b) {
        int f;
        do { f = atomicAdd(&g_flag[t], 0); } while (f == 0);
        atomicAdd(&s_prev, f - 1);
    }
    __syncthreads();
    int base = s_prev;
    int ex = (wid ? wsum[wid - 1] : 0) + x - v;
    if (i < N) g_off[i] = base + ex;
    if (b == nb - 1 && t == 0) g_off[N] = ET;
}

// ---------------- edge pass 2: 2 edges per thread; h2exp halves MUFU ----------------
__device__ __forceinline__ float4 make_rec(int s, const float4& as, const float4& ad) {
    float l0 = as.x + ad.x, l1 = as.y + ad.y, l2 = as.z + ad.z, l3 = as.w + ad.w;
    l0 = l0 > 0.f ? l0 : 0.2f * l0;
    l1 = l1 > 0.f ? l1 : 0.2f * l1;
    l2 = l2 > 0.f ? l2 : 0.2f * l2;
    l3 = l3 > 0.f ? l3 : 0.2f * l3;
    __half2 e01 = h2exp(__floats2half2_rn(l0, l1));   // MUFU.EX2.F16x2 (1 op for 2 exps)
    __half2 e23 = h2exp(__floats2half2_rn(l2, l3));
    float4 rec;
    rec.x = __int_as_float(s);
    rec.y = __uint_as_float(*(const unsigned int*)&e01);
    rec.z = __uint_as_float(*(const unsigned int*)&e23);
    rec.w = 0.0f;
    return rec;
}

__global__ void edge_pass2(const int* __restrict__ e32, int N, int E) {
    int p = blockIdx.x * blockDim.x + threadIdx.x;
    int ET = E + N;
    int e0 = 2 * p, e1 = 2 * p + 1;
    if (e0 >= ET) return;
    bool has1 = (e1 < ET);
    int s0, d0, s1 = 0, d1 = 0;
    if (e1 < E) {
        if (g_is64) {
            int4 vs = *(const int4*)&e32[4 * p];
            int4 vd = *(const int4*)&e32[2 * E + 4 * p];
            s0 = vs.x; s1 = vs.z; d0 = vd.x; d1 = vd.z;
        } else {
            int2 vs = *(const int2*)&e32[2 * p];
            int2 vd = *(const int2*)&e32[E + 2 * p];
            s0 = vs.x; s1 = vs.y; d0 = vd.x; d1 = vd.y;
        }
    } else if (e0 >= E) {
        s0 = d0 = e0 - E;
        s1 = d1 = e1 - E;
    } else {
        if (e0 < E) {
            s0 = g_is64 ? e32[2 * e0] : e32[e0];
            d0 = g_is64 ? e32[2 * E + 2 * e0] : e32[E + e0];
        } else { s0 = d0 = e0 - E; }
        if (has1) {
            if (e1 < E) {
                s1 = g_is64 ? e32[2 * e1] : e32[e1];
                d1 = g_is64 ? e32[2 * E + 2 * e1] : e32[E + e1];
            } else { s1 = d1 = e1 - E; }
        }
    }
    float4 as0 = *(const float4*)&g_asrc[s0 * 4];
    float4 ad0 = *(const float4*)&g_adst[d0 * 4];
    float4 as1, ad1;
    if (has1) {
        as1 = *(const float4*)&g_asrc[s1 * 4];
        ad1 = *(const float4*)&g_adst[d1 * 4];
    }
    int2 rk = has1 ? *(const int2*)&g_rank[e0] : make_int2(g_rank[e0], 0);
    float4 rec0 = make_rec(s0, as0, ad0);
    g_pack[g_off[d0] + rk.x] = rec0;
    if (has1) {
        float4 rec1 = make_rec(s1, as1, ad1);
        g_pack[g_off[d1] + rk.y] = rec1;
    }
}

// ---------------- warp-per-dst-node aggregation; segsum computed in-loop ----------------
__global__ void aggregate_kernel(const float* __restrict__ bias,
                                 float* __restrict__ out, int N) {
    int gw = (blockIdx.x * blockDim.x + threadIdx.x) >> 5;
    int lane = threadIdx.x & 31;
    if (gw >= N) return;
    int beg = g_off[gw], end = g_off[gw + 1];
    float a00 = 0.f, a01 = 0.f, a10 = 0.f, a11 = 0.f;
    float a20 = 0.f, a21 = 0.f, a30 = 0.f, a31 = 0.f;
    float s0 = 0.f, s1 = 0.f, s2 = 0.f, s3 = 0.f;
    for (int j = beg; j < end; j++) {
        float4 rec = g_pack[j];
        int s = __float_as_int(rec.x);
        unsigned int u01 = __float_as_uint(rec.y);
        unsigned int u23 = __float_as_uint(rec.z);
        float2 w01 = __half22float2(*(const __half2*)&u01);
        float2 w23 = __half22float2(*(const __half2*)&u23);
        const __half2* xr = (const __half2*)(g_xh + s * HC);
        float2 v0 = __half22float2(xr[lane]);
        float2 v1 = __half22float2(xr[32 + lane]);
        float2 v2 = __half22float2(xr[64 + lane]);
        float2 v3 = __half22float2(xr[96 + lane]);
        a00 += w01.x * v0.x; a01 += w01.x * v0.y;
        a10 += w01.y * v1.x; a11 += w01.y * v1.y;
        a20 += w23.x * v2.x; a21 += w23.x * v2.y;
        a30 += w23.y * v3.x; a31 += w23.y * v3.y;
        s0 += w01.x; s1 += w01.y; s2 += w23.x; s3 += w23.y;
    }
    float n0 = 0.25f / (s0 + 1e-16f);
    float n1 = 0.25f / (s1 + 1e-16f);
    float n2 = 0.25f / (s2 + 1e-16f);
    float n3 = 0.25f / (s3 + 1e-16f);
    int c = 2 * lane;
    float o0 = a00 * n0 + a10 * n1 + a20 * n2 + a30 * n3 + bias[c];
    float o1 = a01 * n0 + a11 * n1 + a21 * n2 + a31 * n3 + bias[c + 1];
    *(float2*)&out[gw * 64 + c] = make_float2(o0, o1);
}

// ---------------- launch ----------------
extern "C" void kernel_launch(void* const* d_in, const int* in_sizes, int n_in,
                              void* d_out, int out_size) {
    const float* meta_x  = (const float*)d_in[0];
    const int*   edge32  = (const int*)d_in[1];
    const float* W       = (const float*)d_in[2];
    const float* att_src = (const float*)d_in[3];
    const float* att_dst = (const float*)d_in[4];
    const float* bias    = (const float*)d_in[5];
    float*       out     = (float*)d_out;

    int N  = in_sizes[0] / 64;
    int E  = in_sizes[1] / 2;
    int ET = E + N;
    int nb = (N + 1023) / 1024;
    int np = (ET + 1) / 2;                       // edge pairs
    int degBlocks  = (np + 511) / 512;           // degree role blocks (512 thr)
    int gemmBlocks = (N + 63) / 64;

    detect_init_wh_kernel<<<(N + 255) / 256, 256>>>(edge32, W, N);
    gemm_degree_kernel<<<degBlocks + gemmBlocks, 512>>>(meta_x, att_src, att_dst,
                                                        edge32, N, E, degBlocks, gemmBlocks);
    scan_lookback<<<nb, 1024>>>(N, ET, nb);
    edge_pass2<<<(np + 255) / 256, 256>>>(edge32, N, E);
    aggregate_kernel<<<(N * 32 + 255) / 256, 256>>>(bias, out, N);
}